// round 10
// baseline (speedup 1.0000x reference)
#include <cuda_runtime.h>
#include <math.h>
#include <stdint.h>

// ---------------- problem constants ----------------
#define BB 4
#define LL 4096
#define EE 512
#define FF 2049
#define HH 8
#define DD 64
#define FFTM 2048          // half-size complex FFT length

// ---------------- scratch (device globals; allocation-free) ----------------
__device__ float g_xn[BB * LL * EE];       // layernormed x       [B][L][E]
__device__ float g_xt[BB * EE * LL];       // transposed          [B][E][L] (reused for irfft output)
__device__ float g_xr[BB * FF * EE];       // rfft real           [B][F][E]
__device__ float g_xi[BB * FF * EE];       // rfft imag
__device__ float g_Qr[BB * FF * EE];
__device__ float g_Qi[BB * FF * EE];
__device__ float g_Kr[BB * FF * EE];
__device__ float g_Ki[BB * FF * EE];
__device__ float g_Vr[BB * FF * EE];
__device__ float g_Vi[BB * FF * EE];
__device__ float g_Or[BB * FF * EE];       // attention out real  [B][F][E]
__device__ float g_Oi[BB * FF * EE];
__device__ float g_y [BB * LL * EE];       // irfft result        [B][L][E]
__device__ float2 g_twS[1024];             // exp(-2*pi*i*p/2048)
__device__ float2 g_twP[FF];               // exp(-pi*i*k/2048)

// ---------------- tf32 helpers ----------------
__device__ __forceinline__ float tf32r(float x) {
    unsigned u;
    asm("cvt.rna.tf32.f32 %0, %1;" : "=r"(u) : "f"(x));
    return __uint_as_float(u);
}
__device__ __forceinline__ void mma8(float* c, const float* a, const float* b) {
    asm volatile(
        "mma.sync.aligned.m16n8k8.row.col.f32.tf32.tf32.f32 "
        "{%0,%1,%2,%3},{%4,%5,%6,%7},{%8,%9},{%0,%1,%2,%3};"
        : "+f"(c[0]), "+f"(c[1]), "+f"(c[2]), "+f"(c[3])
        : "r"(__float_as_uint(a[0])), "r"(__float_as_uint(a[1])),
          "r"(__float_as_uint(a[2])), "r"(__float_as_uint(a[3])),
          "r"(__float_as_uint(b[0])), "r"(__float_as_uint(b[1])));
}

// ---------------- twiddle table init ----------------
__global__ void twiddle_init()
{
    int t = blockIdx.x * 256 + threadIdx.x;
    if (t < 1024) {
        float sn, cs; sincospif(-(float)t * (1.0f / 1024.0f), &sn, &cs);
        g_twS[t] = make_float2(cs, sn);
    }
    if (t < FF) {
        float sn, cs; sincospif(-(float)t * (1.0f / 2048.0f), &sn, &cs);
        g_twP[t] = make_float2(cs, sn);
    }
}

// ---------------- LayerNorm ----------------
__global__ void ln_kernel(const float* __restrict__ x,
                          const float* __restrict__ gam,
                          const float* __restrict__ bet)
{
    __shared__ float sa[8], sb[8];
    int row = blockIdx.x;
    const float* xr = x + (size_t)row * EE;
    float* o = g_xn + (size_t)row * EE;
    int t = threadIdx.x;
    float v0 = xr[t], v1 = xr[t + 256];
    float s = v0 + v1, s2 = v0 * v0 + v1 * v1;
#pragma unroll
    for (int off = 16; off; off >>= 1) {
        s  += __shfl_xor_sync(0xffffffffu, s,  off);
        s2 += __shfl_xor_sync(0xffffffffu, s2, off);
    }
    if ((t & 31) == 0) { sa[t >> 5] = s; sb[t >> 5] = s2; }
    __syncthreads();
    s = 0.f; s2 = 0.f;
#pragma unroll
    for (int i = 0; i < 8; i++) { s += sa[i]; s2 += sb[i]; }
    float mean = s * (1.0f / EE);
    float var  = s2 * (1.0f / EE) - mean * mean;
    float rs   = rsqrtf(var + 1e-5f);
    o[t]       = (v0 - mean) * rs * gam[t]       + bet[t];
    o[t + 256] = (v1 - mean) * rs * gam[t + 256] + bet[t + 256];
}

// ---------------- transposes ----------------
__global__ void transpose_LE_to_EL()
{
    __shared__ float tile[32][33];
    int b  = blockIdx.z;
    int e0 = blockIdx.x * 32;
    int l0 = blockIdx.y * 32;
    const float* s = g_xn + ((size_t)b * LL + l0) * EE + e0;
    for (int rr = threadIdx.y; rr < 32; rr += 8)
        tile[rr][threadIdx.x] = s[(size_t)rr * EE + threadIdx.x];
    __syncthreads();
    float* d = g_xt + ((size_t)b * EE + e0) * LL + l0;
    for (int rr = threadIdx.y; rr < 32; rr += 8)
        d[(size_t)rr * LL + threadIdx.x] = tile[threadIdx.x][rr];
}

__global__ void transpose_EL_to_LE()
{
    __shared__ float tile[32][33];
    int b  = blockIdx.z;
    int l0 = blockIdx.x * 32;
    int e0 = blockIdx.y * 32;
    const float* s = g_xt + ((size_t)b * EE + e0) * LL + l0;
    for (int rr = threadIdx.y; rr < 32; rr += 8)
        tile[rr][threadIdx.x] = s[(size_t)rr * LL + threadIdx.x];
    __syncthreads();
    float* d = g_y + ((size_t)b * LL + l0) * EE + e0;
    for (int rr = threadIdx.y; rr < 32; rr += 8)
        d[(size_t)rr * EE + threadIdx.x] = tile[threadIdx.x][rr];
}

// ---------------- Stockham FFT (complex, length 2048, 256 threads) ----------------
__device__ __forceinline__ float2* fft_stockham2048(float2* src, float2* dst,
                                                    const float2* __restrict__ tw, int t)
{
#pragma unroll 1
    for (int stage = 0; stage < 11; stage++) {
        int s = 1 << stage;
#pragma unroll
        for (int i = 0; i < 4; i++) {
            int j = t + (i << 8);
            int p = j >> stage;
            int q = j & (s - 1);
            float2 u = src[q + (p << stage)];
            float2 v = src[q + ((p + (1024 >> stage)) << stage)];
            float2 ss = make_float2(u.x + v.x, u.y + v.y);
            float2 dd = make_float2(u.x - v.x, u.y - v.y);
            float2 w  = tw[p << stage];
            int od = q + (p << (stage + 1));
            dst[od]     = ss;
            dst[od + s] = make_float2(dd.x * w.x - dd.y * w.y,
                                      dd.x * w.y + dd.y * w.x);
        }
        __syncthreads();
        float2* tmp = src; src = dst; dst = tmp;
    }
    return src;
}

__global__ void rfft_kernel()
{
    __shared__ float2 bufA[FFTM], bufB[FFTM];
    __shared__ float2 tw[1024];
    int t  = threadIdx.x;
    int be = blockIdx.x;
    int b  = be >> 9, e = be & 511;

    const float2* src = (const float2*)(g_xt + (size_t)be * LL);
#pragma unroll
    for (int i = 0; i < 8; i++) bufA[t + (i << 8)] = src[t + (i << 8)];
#pragma unroll
    for (int i = 0; i < 4; i++) tw[t + (i << 8)] = g_twS[t + (i << 8)];
    __syncthreads();
    float2* Z = fft_stockham2048(bufA, bufB, tw, t);

    const float scale = 1.0f / 64.0f;
    for (int k = t; k <= FFTM; k += 256) {
        float2 zk = Z[k & (FFTM - 1)];
        float2 zm = Z[(FFTM - k) & (FFTM - 1)];
        float Er  = 0.5f * (zk.x + zm.x);
        float Eii = 0.5f * (zk.y - zm.y);
        float Or0 = 0.5f * (zk.x - zm.x);
        float Oi0 = 0.5f * (zk.y + zm.y);
        float2 w = g_twP[k];
        float ux = w.x * Or0 - w.y * Oi0;
        float uy = w.x * Oi0 + w.y * Or0;
        size_t g = ((size_t)b * FF + k) * EE + e;
        g_xr[g] = (Er  + uy) * scale;
        g_xi[g] = (Eii - ux) * scale;
    }
}

__global__ void irfft_kernel()
{
    __shared__ float2 bufA[FFTM], bufB[FFTM];
    __shared__ float2 tw[1024];
    int t  = threadIdx.x;
    int be = blockIdx.x;
    int b  = be >> 9, e = be & 511;

#pragma unroll
    for (int i = 0; i < 4; i++) {
        float2 w = g_twS[t + (i << 8)];
        tw[t + (i << 8)] = make_float2(w.x, -w.y);     // conj -> e^{+}
    }
    for (int k = t; k < FFTM; k += 256) {
        size_t gk = ((size_t)b * FF + k) * EE + e;
        size_t gm = ((size_t)b * FF + (FFTM - k)) * EE + e;
        float Xr_k = g_Or[gk];
        float Xi_k = (k == 0) ? 0.0f : g_Oi[gk];
        float Xr_m = g_Or[gm];
        float Xi_m = (k == 0) ? 0.0f : g_Oi[gm];
        float Er  = 0.5f * (Xr_k + Xr_m);
        float Ei  = 0.5f * (Xi_k - Xi_m);
        float Or0 = 0.5f * (Xr_k - Xr_m);
        float Oi0 = 0.5f * (Xi_k + Xi_m);
        float2 w = g_twP[k];
        float cs = w.x, sn = -w.y;
        float ux = cs * Or0 - sn * Oi0;
        float uy = cs * Oi0 + sn * Or0;
        bufA[k] = make_float2(Er - uy, Ei + ux);
    }
    __syncthreads();
    float2* w = fft_stockham2048(bufA, bufB, tw, t);

    float2* out = (float2*)(g_xt + (size_t)be * LL);
    const float sc = 1.0f / 32.0f;
#pragma unroll
    for (int i = 0; i < 8; i++) {
        int n = t + (i << 8);
        float2 z = w[n];
        out[n] = make_float2(z.x * sc, z.y * sc);
    }
}

// ---------------- tf32 tensor-core GEMM (mma.sync), batched over grid.z ----------------
// block tile 128m x 64n, k-stage 32.  8 warps: 4x2 grid of 32x32 warp tiles.
struct GemmPtrs { const float *A, *W, *bias; float *C; };
struct GemmBatch { GemmPtrs g[6]; };

__global__ void __launch_bounds__(256) gemm_tc(GemmBatch batch, int M)
{
    __shared__ float sA[128 * 36];
    __shared__ float sB[64 * 36];
    GemmPtrs gp = batch.g[blockIdx.z];
    int m0 = blockIdx.x * 128, n0 = blockIdx.y * 64;
    int t = threadIdx.x, lane = t & 31, w = t >> 5;
    int g = lane >> 2, t4 = lane & 3;
    int wm = w >> 1, wn = w & 1;
    float acc[2][4][4] = {};

    for (int k0 = 0; k0 < 512; k0 += 32) {
#pragma unroll
        for (int i = 0; i < 4; i++) {
            int id = t + i * 256;
            int r = id >> 3, kq = (id & 7) * 4;
            float4 v = make_float4(0.f, 0.f, 0.f, 0.f);
            if (m0 + r < M) v = *(const float4*)&gp.A[(size_t)(m0 + r) * 512 + k0 + kq];
            float* d = &sA[r * 36 + kq];
            d[0] = tf32r(v.x); d[1] = tf32r(v.y); d[2] = tf32r(v.z); d[3] = tf32r(v.w);
        }
#pragma unroll
        for (int i = 0; i < 2; i++) {
            int id = t + i * 256;
            int r = id >> 3, kq = (id & 7) * 4;
            float4 v = *(const float4*)&gp.W[(size_t)(n0 + r) * 512 + k0 + kq];
            float* d = &sB[r * 36 + kq];
            d[0] = tf32r(v.x); d[1] = tf32r(v.y); d[2] = tf32r(v.z); d[3] = tf32r(v.w);
        }
        __syncthreads();
#pragma unroll
        for (int ks = 0; ks < 4; ks++) {
            int kk = ks * 8 + t4;
            float a[2][4];
#pragma unroll
            for (int mt = 0; mt < 2; mt++) {
                int row = wm * 32 + mt * 16 + g;
                a[mt][0] = sA[row * 36 + kk];
                a[mt][1] = sA[(row + 8) * 36 + kk];
                a[mt][2] = sA[row * 36 + kk + 4];
                a[mt][3] = sA[(row + 8) * 36 + kk + 4];
            }
#pragma unroll
            for (int nt = 0; nt < 4; nt++) {
                int col = wn * 32 + nt * 8 + g;
                float b[2] = { sB[col * 36 + kk], sB[col * 36 + kk + 4] };
                mma8(acc[0][nt], a[0], b);
                mma8(acc[1][nt], a[1], b);
            }
        }
        __syncthreads();
    }
#pragma unroll
    for (int nt = 0; nt < 4; nt++) {
        int col = n0 + wn * 32 + nt * 8 + 2 * t4;
        float b0 = gp.bias ? gp.bias[col] : 0.f;
        float b1 = gp.bias ? gp.bias[col + 1] : 0.f;
#pragma unroll
        for (int mt = 0; mt < 2; mt++) {
            int row = m0 + wm * 32 + mt * 16 + g;
            if (row < M) {
                float2 v = make_float2(acc[mt][nt][0] + b0, acc[mt][nt][1] + b1);
                *(float2*)&gp.C[(size_t)row * 512 + col] = v;
            }
            if (row + 8 < M) {
                float2 v = make_float2(acc[mt][nt][2] + b0, acc[mt][nt][3] + b1);
                *(float2*)&gp.C[(size_t)(row + 8) * 512 + col] = v;
            }
        }
    }
}

// ---------------- tf32 tensor-core flash attention ----------------
// block: 256 thr, one (b,h), q-tile 128, k-tile 64.
// K and V resident simultaneously -> single load phase per iteration, 4 syncs.
#define SQ_LD 68
#define ATTN_FLOATS (2 * 128 * SQ_LD + 4 * 64 * SQ_LD + 128 * SQ_LD + 3 * 128)
#define ATTN_SMEM (ATTN_FLOATS * 4)
__global__ void __launch_bounds__(256, 1) attn_tc(
    const float* __restrict__ Qr, const float* __restrict__ Qi,
    const float* __restrict__ Kr, const float* __restrict__ Ki,
    const float* __restrict__ Vr, const float* __restrict__ Vi,
    float* __restrict__ Outr, float* __restrict__ Outi)
{
    extern __shared__ float sm[];
    float* sQr = sm;                        // [128][68]
    float* sQi = sQr + 128 * SQ_LD;
    float* sKr = sQi + 128 * SQ_LD;         // [64][68]  K: [f][d]
    float* sKi = sKr + 64 * SQ_LD;
    float* sVr = sKi + 64 * SQ_LD;          // [64][68]  V^T: [d][f]
    float* sVi = sVr + 64 * SQ_LD;
    float* sS  = sVi + 64 * SQ_LD;          // [128][68] S then P
    float* sMm = sS + 128 * SQ_LD;
    float* sLl = sMm + 128;
    float* sAl = sLl + 128;

    int bh = blockIdx.y;
    int b = bh >> 3, h = bh & 7;
    int q0 = blockIdx.x * 128;
    int t = threadIdx.x, lane = t & 31, w = t >> 5;
    int g = lane >> 2, t4 = lane & 3;
    int wm = w >> 1, wn = w & 1;
    const size_t base = (size_t)b * FF * EE + h * DD;

    if (t < 128) { sMm[t] = -1e30f; sLl[t] = 0.f; }
    for (int idx = t; idx < 8192; idx += 256) {
        int q = idx >> 6, d = idx & 63;
        int gq = q0 + q;
        float vr = 0.f, vi = 0.f;
        if (gq < FF) {
            size_t gg = base + (size_t)gq * EE + d;
            vr = Qr[gg] * 0.125f; vi = Qi[gg] * 0.125f;
        }
        sQr[q * SQ_LD + d] = tf32r(vr);
        sQi[q * SQ_LD + d] = tf32r(vi);
    }

    float accR[2][4][4] = {}, accI[2][4][4] = {};

    for (int f0 = 0; f0 < 2112; f0 += 64) {
        __syncthreads();   // protect sK/sV/sS rewrite vs previous iteration's reads
        // load K tile [f][d] and V tile transposed [d][f] in one phase (max MLP)
        for (int idx = t; idx < 4096; idx += 256) {
            int f = idx >> 6, d = idx & 63;
            int gf = f0 + f;
            float kr = 0.f, ki = 0.f, vr = 0.f, vi = 0.f;
            if (gf < FF) {
                size_t gg = base + (size_t)gf * EE + d;
                kr = Kr[gg]; ki = Ki[gg];
                vr = Vr[gg]; vi = Vi[gg];
            }
            sKr[f * SQ_LD + d] = tf32r(kr);
            sKi[f * SQ_LD + d] = tf32r(ki);
            sVr[d * SQ_LD + f] = tf32r(vr);
            sVi[d * SQ_LD + f] = tf32r(vi);
        }
        __syncthreads();

        // S = Qr Kr^T + Qi Ki^T
        float sacc[2][4][4] = {};
#pragma unroll
        for (int ks = 0; ks < 8; ks++) {
            int kk = ks * 8 + t4;
            float a[2][4];
#pragma unroll
            for (int mt = 0; mt < 2; mt++) {
                int row = wm * 32 + mt * 16 + g;
                a[mt][0] = sQr[row * SQ_LD + kk];
                a[mt][1] = sQr[(row + 8) * SQ_LD + kk];
                a[mt][2] = sQr[row * SQ_LD + kk + 4];
                a[mt][3] = sQr[(row + 8) * SQ_LD + kk + 4];
            }
#pragma unroll
            for (int nt = 0; nt < 4; nt++) {
                int f = wn * 32 + nt * 8 + g;
                float bfr[2] = { sKr[f * SQ_LD + kk], sKr[f * SQ_LD + kk + 4] };
                mma8(sacc[0][nt], a[0], bfr);
                mma8(sacc[1][nt], a[1], bfr);
            }
        }
#pragma unroll
        for (int ks = 0; ks < 8; ks++) {
            int kk = ks * 8 + t4;
            float a[2][4];
#pragma unroll
            for (int mt = 0; mt < 2; mt++) {
                int row = wm * 32 + mt * 16 + g;
                a[mt][0] = sQi[row * SQ_LD + kk];
                a[mt][1] = sQi[(row + 8) * SQ_LD + kk];
                a[mt][2] = sQi[row * SQ_LD + kk + 4];
                a[mt][3] = sQi[(row + 8) * SQ_LD + kk + 4];
            }
#pragma unroll
            for (int nt = 0; nt < 4; nt++) {
                int f = wn * 32 + nt * 8 + g;
                float bfi[2] = { sKi[f * SQ_LD + kk], sKi[f * SQ_LD + kk + 4] };
                mma8(sacc[0][nt], a[0], bfi);
                mma8(sacc[1][nt], a[1], bfi);
            }
        }
        // write S
#pragma unroll
        for (int mt = 0; mt < 2; mt++) {
            int row = wm * 32 + mt * 16 + g;
#pragma unroll
            for (int nt = 0; nt < 4; nt++) {
                int col = wn * 32 + nt * 8 + 2 * t4;
                *(float2*)&sS[row * SQ_LD + col]       = make_float2(sacc[mt][nt][0], sacc[mt][nt][1]);
                *(float2*)&sS[(row + 8) * SQ_LD + col] = make_float2(sacc[mt][nt][2], sacc[mt][nt][3]);
            }
        }
        __syncthreads();

        // softmax: 2 threads per row, 32 cols each
        {
            int r = t >> 1, c0 = (t & 1) * 32;
            float4 v[8];
            float mx = -1e30f;
#pragma unroll
            for (int j = 0; j < 8; j++) {
                v[j] = *(float4*)&sS[r * SQ_LD + c0 + j * 4];
                int cb = f0 + c0 + j * 4;
                if (cb + 0 < FF) mx = fmaxf(mx, v[j].x);
                if (cb + 1 < FF) mx = fmaxf(mx, v[j].y);
                if (cb + 2 < FF) mx = fmaxf(mx, v[j].z);
                if (cb + 3 < FF) mx = fmaxf(mx, v[j].w);
            }
            mx = fmaxf(mx, __shfl_xor_sync(0xffffffffu, mx, 1));
            float mold = sMm[r];
            float mnew = fmaxf(mold, mx);
            float al = __expf(mold - mnew);
            float sum = 0.f;
#pragma unroll
            for (int j = 0; j < 8; j++) {
                int cb = f0 + c0 + j * 4;
                float p0 = (cb + 0 < FF) ? __expf(v[j].x - mnew) : 0.f;
                float p1 = (cb + 1 < FF) ? __expf(v[j].y - mnew) : 0.f;
                float p2 = (cb + 2 < FF) ? __expf(v[j].z - mnew) : 0.f;
                float p3 = (cb + 3 < FF) ? __expf(v[j].w - mnew) : 0.f;
                sum += p0 + p1 + p2 + p3;
                v[j] = make_float4(tf32r(p0), tf32r(p1), tf32r(p2), tf32r(p3));
            }
            sum += __shfl_xor_sync(0xffffffffu, sum, 1);
            if ((t & 1) == 0) {
                sMm[r] = mnew;
                sLl[r] = sLl[r] * al + sum;
                sAl[r] = al;
            }
#pragma unroll
            for (int j = 0; j < 8; j++)
                *(float4*)&sS[r * SQ_LD + c0 + j * 4] = v[j];
        }
        __syncthreads();

        // rescale O accumulators
#pragma unroll
        for (int mt = 0; mt < 2; mt++) {
            int row = wm * 32 + mt * 16 + g;
            float a0 = sAl[row], a1 = sAl[row + 8];
#pragma unroll
            for (int nt = 0; nt < 4; nt++) {
                accR[mt][nt][0] *= a0; accR[mt][nt][1] *= a0;
                accR[mt][nt][2] *= a1; accR[mt][nt][3] *= a1;
                accI[mt][nt][0] *= a0; accI[mt][nt][1] *= a0;
                accI[mt][nt][2] *= a1; accI[mt][nt][3] *= a1;
            }
        }

        // O += P @ V  (r and i) -- V already resident
#pragma unroll
        for (int ks = 0; ks < 8; ks++) {
            int kk = ks * 8 + t4;
            float a[2][4];
#pragma unroll
            for (int mt = 0; mt < 2; mt++) {
                int row = wm * 32 + mt * 16 + g;
                a[mt][0] = sS[row * SQ_LD + kk];
                a[mt][1] = sS[(row + 8) * SQ_LD + kk];
                a[mt][2] = sS[row * SQ_LD + kk + 4];
                a[mt][3] = sS[(row + 8) * SQ_LD + kk + 4];
            }
#pragma unroll
            for (int nt = 0; nt < 4; nt++) {
                int d = wn * 32 + nt * 8 + g;
                float br[2] = { sVr[d * SQ_LD + kk], sVr[d * SQ_LD + kk + 4] };
                mma8(accR[0][nt], a[0], br);
                mma8(accR[1][nt], a[1], br);
                float bi[2] = { sVi[d * SQ_LD + kk], sVi[d * SQ_LD + kk + 4] };
                mma8(accI[0][nt], a[0], bi);
                mma8(accI[1][nt], a[1], bi);
            }
        }
    }
    __syncthreads();

    // write output (divide by l)
#pragma unroll
    for (int mt = 0; mt < 2; mt++) {
        int row = wm * 32 + mt * 16 + g;
        float li0 = 1.0f / sLl[row];
        float li1 = 1.0f / sLl[row + 8];
        int q  = q0 + row;
#pragma unroll
        for (int nt = 0; nt < 4; nt++) {
            int col = wn * 32 + nt * 8 + 2 * t4;
            if (q < FF) {
                size_t gg = base + (size_t)q * EE + col;
                *(float2*)&Outr[gg] = make_float2(accR[mt][nt][0] * li0, accR[mt][nt][1] * li0);
                *(float2*)&Outi[gg] = make_float2(accI[mt][nt][0] * li0, accI[mt][nt][1] * li0);
            }
            if (q + 8 < FF) {
                size_t gg = base + (size_t)(q + 8) * EE + col;
                *(float2*)&Outr[gg] = make_float2(accR[mt][nt][2] * li1, accR[mt][nt][3] * li1);
                *(float2*)&Outi[gg] = make_float2(accI[mt][nt][2] * li1, accI[mt][nt][3] * li1);
            }
        }
    }
}

// ---------------- host launcher ----------------
extern "C" void kernel_launch(void* const* d_in, const int* in_sizes, int n_in,
                              void* d_out, int out_size)
{
    const float* x    = (const float*)d_in[0];
    const float* gam  = (const float*)d_in[1];
    const float* bet  = (const float*)d_in[2];
    const float* Wq_r = (const float*)d_in[3];
    const float* bq_r = (const float*)d_in[4];
    const float* Wq_i = (const float*)d_in[5];
    const float* bq_i = (const float*)d_in[6];
    const float* Wk_r = (const float*)d_in[7];
    const float* bk_r = (const float*)d_in[8];
    const float* Wk_i = (const float*)d_in[9];
    const float* bk_i = (const float*)d_in[10];
    const float* Wv_r = (const float*)d_in[11];
    const float* bv_r = (const float*)d_in[12];
    const float* Wv_i = (const float*)d_in[13];
    const float* bv_i = (const float*)d_in[14];
    const float* Wo   = (const float*)d_in[15];
    float* out = (float*)d_out;

    static int attr_set = 0;
    if (!attr_set) {
        cudaFuncSetAttribute(attn_tc, cudaFuncAttributeMaxDynamicSharedMemorySize, ATTN_SMEM);
        attr_set = 1;
    }

    float *p_xr, *p_xi, *p_Qr, *p_Qi, *p_Kr, *p_Ki, *p_Vr, *p_Vi, *p_Or, *p_Oi, *p_y;
    cudaGetSymbolAddress((void**)&p_xr, g_xr);
    cudaGetSymbolAddress((void**)&p_xi, g_xi);
    cudaGetSymbolAddress((void**)&p_Qr, g_Qr);
    cudaGetSymbolAddress((void**)&p_Qi, g_Qi);
    cudaGetSymbolAddress((void**)&p_Kr, g_Kr);
    cudaGetSymbolAddress((void**)&p_Ki, g_Ki);
    cudaGetSymbolAddress((void**)&p_Vr, g_Vr);
    cudaGetSymbolAddress((void**)&p_Vi, g_Vi);
    cudaGetSymbolAddress((void**)&p_Or, g_Or);
    cudaGetSymbolAddress((void**)&p_Oi, g_Oi);
    cudaGetSymbolAddress((void**)&p_y,  g_y);

    const int MF = BB * FF;      // 8196
    const int ML = BB * LL;      // 16384

    twiddle_init<<<9, 256>>>();
    ln_kernel<<<BB * LL, 256>>>(x, gam, bet);
    {
        dim3 g(EE / 32, LL / 32, BB), blk(32, 8);
        transpose_LE_to_EL<<<g, blk>>>();
    }
    rfft_kernel<<<BB * EE, 256>>>();
    {
        GemmBatch gb;
        gb.g[0] = { p_xr, Wq_r, bq_r, p_Qr };
        gb.g[1] = { p_xi, Wq_i, bq_i, p_Qi };
        gb.g[2] = { p_xr, Wk_r, bk_r, p_Kr };
        gb.g[3] = { p_xi, Wk_i, bk_i, p_Ki };
        gb.g[4] = { p_xr, Wv_r, bv_r, p_Vr };
        gb.g[5] = { p_xi, Wv_i, bv_i, p_Vi };
        dim3 g((MF + 127) / 128, 8, 6);
        gemm_tc<<<g, 256>>>(gb, MF);
    }
    {
        dim3 g((FF + 127) / 128, BB * HH);
        attn_tc<<<g, 256, ATTN_SMEM>>>(p_Qr, p_Qi, p_Kr, p_Ki, p_Vr, p_Vi, p_Or, p_Oi);
    }
    irfft_kernel<<<BB * EE, 256>>>();
    {
        dim3 g(LL / 32, EE / 32, BB), blk(32, 8);
        transpose_EL_to_LE<<<g, blk>>>();
    }
    {
        GemmBatch gb;
        gb.g[0] = { p_y, Wo, nullptr, out };
        gb.g[1] = gb.g[0]; gb.g[2] = gb.g[0]; gb.g[3] = gb.g[0];
        gb.g[4] = gb.g[0]; gb.g[5] = gb.g[0];
        dim3 g((ML + 127) / 128, 8, 1);
        gemm_tc<<<g, 256>>>(gb, ML);
    }
}

// round 11
// speedup vs baseline: 1.2350x; 1.2350x over previous
#include <cuda_runtime.h>
#include <math.h>
#include <stdint.h>

// ---------------- problem constants ----------------
#define BB 4
#define LL 4096
#define EE 512
#define FF 2049
#define HH 8
#define DD 64
#define FFTM 2048          // half-size complex FFT length

// ---------------- scratch (device globals; allocation-free) ----------------
__device__ float g_xn[BB * LL * EE];       // layernormed x       [B][L][E]
__device__ float g_xt[BB * EE * LL];       // transposed          [B][E][L] (reused for irfft output)
__device__ float g_xr[BB * FF * EE];       // rfft real           [B][F][E]
__device__ float g_xi[BB * FF * EE];       // rfft imag
__device__ float g_Qr[BB * FF * EE];
__device__ float g_Qi[BB * FF * EE];
__device__ float g_Kr[BB * FF * EE];
__device__ float g_Ki[BB * FF * EE];
__device__ float g_Vr[BB * FF * EE];
__device__ float g_Vi[BB * FF * EE];
__device__ float g_Or[BB * FF * EE];       // attention out real  [B][F][E]
__device__ float g_Oi[BB * FF * EE];
__device__ float g_y [BB * LL * EE];       // irfft result        [B][L][E]
__device__ float2 g_twS[1024];             // exp(-2*pi*i*p/2048)
__device__ float2 g_twP[FF];               // exp(-pi*i*k/2048)

// ---------------- tf32 helpers ----------------
__device__ __forceinline__ float tf32r(float x) {
    unsigned u;
    asm("cvt.rna.tf32.f32 %0, %1;" : "=r"(u) : "f"(x));
    return __uint_as_float(u);
}
__device__ __forceinline__ void mma8(float* c, const float* a, const float* b) {
    asm volatile(
        "mma.sync.aligned.m16n8k8.row.col.f32.tf32.tf32.f32 "
        "{%0,%1,%2,%3},{%4,%5,%6,%7},{%8,%9},{%0,%1,%2,%3};"
        : "+f"(c[0]), "+f"(c[1]), "+f"(c[2]), "+f"(c[3])
        : "r"(__float_as_uint(a[0])), "r"(__float_as_uint(a[1])),
          "r"(__float_as_uint(a[2])), "r"(__float_as_uint(a[3])),
          "r"(__float_as_uint(b[0])), "r"(__float_as_uint(b[1])));
}

// ---------------- twiddle table init ----------------
__global__ void twiddle_init()
{
    int t = blockIdx.x * 256 + threadIdx.x;
    if (t < 1024) {
        float sn, cs; sincospif(-(float)t * (1.0f / 1024.0f), &sn, &cs);
        g_twS[t] = make_float2(cs, sn);
    }
    if (t < FF) {
        float sn, cs; sincospif(-(float)t * (1.0f / 2048.0f), &sn, &cs);
        g_twP[t] = make_float2(cs, sn);
    }
}

// ---------------- LayerNorm ----------------
__global__ void ln_kernel(const float* __restrict__ x,
                          const float* __restrict__ gam,
                          const float* __restrict__ bet)
{
    __shared__ float sa[8], sb[8];
    int row = blockIdx.x;
    const float* xr = x + (size_t)row * EE;
    float* o = g_xn + (size_t)row * EE;
    int t = threadIdx.x;
    float v0 = xr[t], v1 = xr[t + 256];
    float s = v0 + v1, s2 = v0 * v0 + v1 * v1;
#pragma unroll
    for (int off = 16; off; off >>= 1) {
        s  += __shfl_xor_sync(0xffffffffu, s,  off);
        s2 += __shfl_xor_sync(0xffffffffu, s2, off);
    }
    if ((t & 31) == 0) { sa[t >> 5] = s; sb[t >> 5] = s2; }
    __syncthreads();
    s = 0.f; s2 = 0.f;
#pragma unroll
    for (int i = 0; i < 8; i++) { s += sa[i]; s2 += sb[i]; }
    float mean = s * (1.0f / EE);
    float var  = s2 * (1.0f / EE) - mean * mean;
    float rs   = rsqrtf(var + 1e-5f);
    o[t]       = (v0 - mean) * rs * gam[t]       + bet[t];
    o[t + 256] = (v1 - mean) * rs * gam[t + 256] + bet[t + 256];
}

// ---------------- transposes ----------------
__global__ void transpose_LE_to_EL()
{
    __shared__ float tile[32][33];
    int b  = blockIdx.z;
    int e0 = blockIdx.x * 32;
    int l0 = blockIdx.y * 32;
    const float* s = g_xn + ((size_t)b * LL + l0) * EE + e0;
    for (int rr = threadIdx.y; rr < 32; rr += 8)
        tile[rr][threadIdx.x] = s[(size_t)rr * EE + threadIdx.x];
    __syncthreads();
    float* d = g_xt + ((size_t)b * EE + e0) * LL + l0;
    for (int rr = threadIdx.y; rr < 32; rr += 8)
        d[(size_t)rr * LL + threadIdx.x] = tile[threadIdx.x][rr];
}

__global__ void transpose_EL_to_LE()
{
    __shared__ float tile[32][33];
    int b  = blockIdx.z;
    int l0 = blockIdx.x * 32;
    int e0 = blockIdx.y * 32;
    const float* s = g_xt + ((size_t)b * EE + e0) * LL + l0;
    for (int rr = threadIdx.y; rr < 32; rr += 8)
        tile[rr][threadIdx.x] = s[(size_t)rr * LL + threadIdx.x];
    __syncthreads();
    float* d = g_y + ((size_t)b * LL + l0) * EE + e0;
    for (int rr = threadIdx.y; rr < 32; rr += 8)
        d[(size_t)rr * EE + threadIdx.x] = tile[threadIdx.x][rr];
}

// ---------------- Stockham FFT (complex, length 2048, 256 threads) ----------------
__device__ __forceinline__ float2* fft_stockham2048(float2* src, float2* dst,
                                                    const float2* __restrict__ tw, int t)
{
#pragma unroll 1
    for (int stage = 0; stage < 11; stage++) {
        int s = 1 << stage;
#pragma unroll
        for (int i = 0; i < 4; i++) {
            int j = t + (i << 8);
            int p = j >> stage;
            int q = j & (s - 1);
            float2 u = src[q + (p << stage)];
            float2 v = src[q + ((p + (1024 >> stage)) << stage)];
            float2 ss = make_float2(u.x + v.x, u.y + v.y);
            float2 dd = make_float2(u.x - v.x, u.y - v.y);
            float2 w  = tw[p << stage];
            int od = q + (p << (stage + 1));
            dst[od]     = ss;
            dst[od + s] = make_float2(dd.x * w.x - dd.y * w.y,
                                      dd.x * w.y + dd.y * w.x);
        }
        __syncthreads();
        float2* tmp = src; src = dst; dst = tmp;
    }
    return src;
}

__global__ void rfft_kernel()
{
    __shared__ float2 bufA[FFTM], bufB[FFTM];
    __shared__ float2 tw[1024];
    int t  = threadIdx.x;
    int be = blockIdx.x;
    int b  = be >> 9, e = be & 511;

    const float2* src = (const float2*)(g_xt + (size_t)be * LL);
#pragma unroll
    for (int i = 0; i < 8; i++) bufA[t + (i << 8)] = src[t + (i << 8)];
#pragma unroll
    for (int i = 0; i < 4; i++) tw[t + (i << 8)] = g_twS[t + (i << 8)];
    __syncthreads();
    float2* Z = fft_stockham2048(bufA, bufB, tw, t);

    const float scale = 1.0f / 64.0f;
    for (int k = t; k <= FFTM; k += 256) {
        float2 zk = Z[k & (FFTM - 1)];
        float2 zm = Z[(FFTM - k) & (FFTM - 1)];
        float Er  = 0.5f * (zk.x + zm.x);
        float Eii = 0.5f * (zk.y - zm.y);
        float Or0 = 0.5f * (zk.x - zm.x);
        float Oi0 = 0.5f * (zk.y + zm.y);
        float2 w = g_twP[k];
        float ux = w.x * Or0 - w.y * Oi0;
        float uy = w.x * Oi0 + w.y * Or0;
        size_t g = ((size_t)b * FF + k) * EE + e;
        g_xr[g] = (Er  + uy) * scale;
        g_xi[g] = (Eii - ux) * scale;
    }
}

__global__ void irfft_kernel()
{
    __shared__ float2 bufA[FFTM], bufB[FFTM];
    __shared__ float2 tw[1024];
    int t  = threadIdx.x;
    int be = blockIdx.x;
    int b  = be >> 9, e = be & 511;

#pragma unroll
    for (int i = 0; i < 4; i++) {
        float2 w = g_twS[t + (i << 8)];
        tw[t + (i << 8)] = make_float2(w.x, -w.y);     // conj -> e^{+}
    }
    for (int k = t; k < FFTM; k += 256) {
        size_t gk = ((size_t)b * FF + k) * EE + e;
        size_t gm = ((size_t)b * FF + (FFTM - k)) * EE + e;
        float Xr_k = g_Or[gk];
        float Xi_k = (k == 0) ? 0.0f : g_Oi[gk];
        float Xr_m = g_Or[gm];
        float Xi_m = (k == 0) ? 0.0f : g_Oi[gm];
        float Er  = 0.5f * (Xr_k + Xr_m);
        float Ei  = 0.5f * (Xi_k - Xi_m);
        float Or0 = 0.5f * (Xr_k - Xr_m);
        float Oi0 = 0.5f * (Xi_k + Xi_m);
        float2 w = g_twP[k];
        float cs = w.x, sn = -w.y;
        float ux = cs * Or0 - sn * Oi0;
        float uy = cs * Oi0 + sn * Or0;
        bufA[k] = make_float2(Er - uy, Ei + ux);
    }
    __syncthreads();
    float2* w = fft_stockham2048(bufA, bufB, tw, t);

    float2* out = (float2*)(g_xt + (size_t)be * LL);
    const float sc = 1.0f / 32.0f;
#pragma unroll
    for (int i = 0; i < 8; i++) {
        int n = t + (i << 8);
        float2 z = w[n];
        out[n] = make_float2(z.x * sc, z.y * sc);
    }
}

// ---------------- tf32 tensor-core GEMM (mma.sync), batched over grid.z ----------------
// block tile 128m x 64n, k-stage 32.  8 warps: 4x2 grid of 32x32 warp tiles.
struct GemmPtrs { const float *A, *W, *bias; float *C; };
struct GemmBatch { GemmPtrs g[6]; };

__global__ void __launch_bounds__(256) gemm_tc(GemmBatch batch, int M)
{
    __shared__ float sA[128 * 36];
    __shared__ float sB[64 * 36];
    GemmPtrs gp = batch.g[blockIdx.z];
    int m0 = blockIdx.x * 128, n0 = blockIdx.y * 64;
    int t = threadIdx.x, lane = t & 31, w = t >> 5;
    int g = lane >> 2, t4 = lane & 3;
    int wm = w >> 1, wn = w & 1;
    float acc[2][4][4] = {};

    for (int k0 = 0; k0 < 512; k0 += 32) {
#pragma unroll
        for (int i = 0; i < 4; i++) {
            int id = t + i * 256;
            int r = id >> 3, kq = (id & 7) * 4;
            float4 v = make_float4(0.f, 0.f, 0.f, 0.f);
            if (m0 + r < M) v = *(const float4*)&gp.A[(size_t)(m0 + r) * 512 + k0 + kq];
            float* d = &sA[r * 36 + kq];
            d[0] = tf32r(v.x); d[1] = tf32r(v.y); d[2] = tf32r(v.z); d[3] = tf32r(v.w);
        }
#pragma unroll
        for (int i = 0; i < 2; i++) {
            int id = t + i * 256;
            int r = id >> 3, kq = (id & 7) * 4;
            float4 v = *(const float4*)&gp.W[(size_t)(n0 + r) * 512 + k0 + kq];
            float* d = &sB[r * 36 + kq];
            d[0] = tf32r(v.x); d[1] = tf32r(v.y); d[2] = tf32r(v.z); d[3] = tf32r(v.w);
        }
        __syncthreads();
#pragma unroll
        for (int ks = 0; ks < 4; ks++) {
            int kk = ks * 8 + t4;
            float a[2][4];
#pragma unroll
            for (int mt = 0; mt < 2; mt++) {
                int row = wm * 32 + mt * 16 + g;
                a[mt][0] = sA[row * 36 + kk];
                a[mt][1] = sA[(row + 8) * 36 + kk];
                a[mt][2] = sA[row * 36 + kk + 4];
                a[mt][3] = sA[(row + 8) * 36 + kk + 4];
            }
#pragma unroll
            for (int nt = 0; nt < 4; nt++) {
                int col = wn * 32 + nt * 8 + g;
                float b[2] = { sB[col * 36 + kk], sB[col * 36 + kk + 4] };
                mma8(acc[0][nt], a[0], b);
                mma8(acc[1][nt], a[1], b);
            }
        }
        __syncthreads();
    }
#pragma unroll
    for (int nt = 0; nt < 4; nt++) {
        int col = n0 + wn * 32 + nt * 8 + 2 * t4;
        float b0 = gp.bias ? gp.bias[col] : 0.f;
        float b1 = gp.bias ? gp.bias[col + 1] : 0.f;
#pragma unroll
        for (int mt = 0; mt < 2; mt++) {
            int row = m0 + wm * 32 + mt * 16 + g;
            if (row < M) {
                float2 v = make_float2(acc[mt][nt][0] + b0, acc[mt][nt][1] + b1);
                *(float2*)&gp.C[(size_t)row * 512 + col] = v;
            }
            if (row + 8 < M) {
                float2 v = make_float2(acc[mt][nt][2] + b0, acc[mt][nt][3] + b1);
                *(float2*)&gp.C[(size_t)(row + 8) * 512 + col] = v;
            }
        }
    }
}

// ---------------- tf32 tensor-core flash attention (round-8 layout: 83KB, 2 CTA/SM) ----------------
// block: 256 thr, one (b,h), q-tile 128, k-tile 64.
// warp grid 4m x 2n, warp tile 32x32 (both S and O phases).  K buffers reused for V.
#define SQ_LD 68
#define ATTN_FLOATS (2 * 128 * SQ_LD + 2 * 64 * SQ_LD + 128 * SQ_LD + 3 * 128)
#define ATTN_SMEM (ATTN_FLOATS * 4)
__global__ void __launch_bounds__(256, 1) attn_tc(
    const float* __restrict__ Qr, const float* __restrict__ Qi,
    const float* __restrict__ Kr, const float* __restrict__ Ki,
    const float* __restrict__ Vr, const float* __restrict__ Vi,
    float* __restrict__ Outr, float* __restrict__ Outi)
{
    extern __shared__ float sm[];
    float* sQr = sm;                        // [128][68]
    float* sQi = sQr + 128 * SQ_LD;
    float* sKr = sQi + 128 * SQ_LD;         // [64][68]  K: [f][d], reused for V^T: [d][f]
    float* sKi = sKr + 64 * SQ_LD;
    float* sS  = sKi + 64 * SQ_LD;          // [128][68] S then P
    float* sMm = sS + 128 * SQ_LD;
    float* sLl = sMm + 128;
    float* sAl = sLl + 128;

    int bh = blockIdx.y;
    int b = bh >> 3, h = bh & 7;
    int q0 = blockIdx.x * 128;
    int t = threadIdx.x, lane = t & 31, w = t >> 5;
    int g = lane >> 2, t4 = lane & 3;
    int wm = w >> 1, wn = w & 1;
    const size_t base = (size_t)b * FF * EE + h * DD;

    if (t < 128) { sMm[t] = -1e30f; sLl[t] = 0.f; }
    for (int idx = t; idx < 8192; idx += 256) {
        int q = idx >> 6, d = idx & 63;
        int gq = q0 + q;
        float vr = 0.f, vi = 0.f;
        if (gq < FF) {
            size_t gg = base + (size_t)gq * EE + d;
            vr = Qr[gg] * 0.125f; vi = Qi[gg] * 0.125f;
        }
        sQr[q * SQ_LD + d] = tf32r(vr);
        sQi[q * SQ_LD + d] = tf32r(vi);
    }

    float accR[2][4][4] = {}, accI[2][4][4] = {};

    for (int f0 = 0; f0 < 2112; f0 += 64) {
        __syncthreads();
        // load K tile [f][d]
        for (int idx = t; idx < 4096; idx += 256) {
            int f = idx >> 6, d = idx & 63;
            int gf = f0 + f;
            float vr = 0.f, vi = 0.f;
            if (gf < FF) {
                size_t gg = base + (size_t)gf * EE + d;
                vr = Kr[gg]; vi = Ki[gg];
            }
            sKr[f * SQ_LD + d] = tf32r(vr);
            sKi[f * SQ_LD + d] = tf32r(vi);
        }
        __syncthreads();

        // S = Qr Kr^T + Qi Ki^T
        float sacc[2][4][4] = {};
#pragma unroll
        for (int ks = 0; ks < 8; ks++) {
            int kk = ks * 8 + t4;
            float a[2][4];
#pragma unroll
            for (int mt = 0; mt < 2; mt++) {
                int row = wm * 32 + mt * 16 + g;
                a[mt][0] = sQr[row * SQ_LD + kk];
                a[mt][1] = sQr[(row + 8) * SQ_LD + kk];
                a[mt][2] = sQr[row * SQ_LD + kk + 4];
                a[mt][3] = sQr[(row + 8) * SQ_LD + kk + 4];
            }
#pragma unroll
            for (int nt = 0; nt < 4; nt++) {
                int f = wn * 32 + nt * 8 + g;
                float bfr[2] = { sKr[f * SQ_LD + kk], sKr[f * SQ_LD + kk + 4] };
                mma8(sacc[0][nt], a[0], bfr);
                mma8(sacc[1][nt], a[1], bfr);
            }
        }
#pragma unroll
        for (int ks = 0; ks < 8; ks++) {
            int kk = ks * 8 + t4;
            float a[2][4];
#pragma unroll
            for (int mt = 0; mt < 2; mt++) {
                int row = wm * 32 + mt * 16 + g;
                a[mt][0] = sQi[row * SQ_LD + kk];
                a[mt][1] = sQi[(row + 8) * SQ_LD + kk];
                a[mt][2] = sQi[row * SQ_LD + kk + 4];
                a[mt][3] = sQi[(row + 8) * SQ_LD + kk + 4];
            }
#pragma unroll
            for (int nt = 0; nt < 4; nt++) {
                int f = wn * 32 + nt * 8 + g;
                float bfi[2] = { sKi[f * SQ_LD + kk], sKi[f * SQ_LD + kk + 4] };
                mma8(sacc[0][nt], a[0], bfi);
                mma8(sacc[1][nt], a[1], bfi);
            }
        }
        // write S
#pragma unroll
        for (int mt = 0; mt < 2; mt++) {
            int row = wm * 32 + mt * 16 + g;
#pragma unroll
            for (int nt = 0; nt < 4; nt++) {
                int col = wn * 32 + nt * 8 + 2 * t4;
                *(float2*)&sS[row * SQ_LD + col]       = make_float2(sacc[mt][nt][0], sacc[mt][nt][1]);
                *(float2*)&sS[(row + 8) * SQ_LD + col] = make_float2(sacc[mt][nt][2], sacc[mt][nt][3]);
            }
        }
        __syncthreads();

        // softmax: 2 threads per row, 32 cols each
        {
            int r = t >> 1, c0 = (t & 1) * 32;
            float4 v[8];
            float mx = -1e30f;
#pragma unroll
            for (int j = 0; j < 8; j++) {
                v[j] = *(float4*)&sS[r * SQ_LD + c0 + j * 4];
                int cb = f0 + c0 + j * 4;
                if (cb + 0 < FF) mx = fmaxf(mx, v[j].x);
                if (cb + 1 < FF) mx = fmaxf(mx, v[j].y);
                if (cb + 2 < FF) mx = fmaxf(mx, v[j].z);
                if (cb + 3 < FF) mx = fmaxf(mx, v[j].w);
            }
            mx = fmaxf(mx, __shfl_xor_sync(0xffffffffu, mx, 1));
            float mold = sMm[r];
            float mnew = fmaxf(mold, mx);
            float al = __expf(mold - mnew);
            float sum = 0.f;
#pragma unroll
            for (int j = 0; j < 8; j++) {
                int cb = f0 + c0 + j * 4;
                float p0 = (cb + 0 < FF) ? __expf(v[j].x - mnew) : 0.f;
                float p1 = (cb + 1 < FF) ? __expf(v[j].y - mnew) : 0.f;
                float p2 = (cb + 2 < FF) ? __expf(v[j].z - mnew) : 0.f;
                float p3 = (cb + 3 < FF) ? __expf(v[j].w - mnew) : 0.f;
                sum += p0 + p1 + p2 + p3;
                v[j] = make_float4(tf32r(p0), tf32r(p1), tf32r(p2), tf32r(p3));
            }
            sum += __shfl_xor_sync(0xffffffffu, sum, 1);
            if ((t & 1) == 0) {
                sMm[r] = mnew;
                sLl[r] = sLl[r] * al + sum;
                sAl[r] = al;
            }
#pragma unroll
            for (int j = 0; j < 8; j++)
                *(float4*)&sS[r * SQ_LD + c0 + j * 4] = v[j];
        }
        __syncthreads();

        // rescale O accumulators
#pragma unroll
        for (int mt = 0; mt < 2; mt++) {
            int row = wm * 32 + mt * 16 + g;
            float a0 = sAl[row], a1 = sAl[row + 8];
#pragma unroll
            for (int nt = 0; nt < 4; nt++) {
                accR[mt][nt][0] *= a0; accR[mt][nt][1] *= a0;
                accR[mt][nt][2] *= a1; accR[mt][nt][3] *= a1;
                accI[mt][nt][0] *= a0; accI[mt][nt][1] *= a0;
                accI[mt][nt][2] *= a1; accI[mt][nt][3] *= a1;
            }
        }
        // load V transposed [d][f] into K buffers
        for (int idx = t; idx < 4096; idx += 256) {
            int f = idx >> 6, d = idx & 63;
            int gf = f0 + f;
            float vr = 0.f, vi = 0.f;
            if (gf < FF) {
                size_t gg = base + (size_t)gf * EE + d;
                vr = Vr[gg]; vi = Vi[gg];
            }
            sKr[d * SQ_LD + f] = tf32r(vr);
            sKi[d * SQ_LD + f] = tf32r(vi);
        }
        __syncthreads();

        // O += P @ V  (r and i)
#pragma unroll
        for (int ks = 0; ks < 8; ks++) {
            int kk = ks * 8 + t4;
            float a[2][4];
#pragma unroll
            for (int mt = 0; mt < 2; mt++) {
                int row = wm * 32 + mt * 16 + g;
                a[mt][0] = sS[row * SQ_LD + kk];
                a[mt][1] = sS[(row + 8) * SQ_LD + kk];
                a[mt][2] = sS[row * SQ_LD + kk + 4];
                a[mt][3] = sS[(row + 8) * SQ_LD + kk + 4];
            }
#pragma unroll
            for (int nt = 0; nt < 4; nt++) {
                int d = wn * 32 + nt * 8 + g;
                float br[2] = { sKr[d * SQ_LD + kk], sKr[d * SQ_LD + kk + 4] };
                mma8(accR[0][nt], a[0], br);
                mma8(accR[1][nt], a[1], br);
                float bi[2] = { sKi[d * SQ_LD + kk], sKi[d * SQ_LD + kk + 4] };
                mma8(accI[0][nt], a[0], bi);
                mma8(accI[1][nt], a[1], bi);
            }
        }
    }
    __syncthreads();

    // write output (divide by l)
#pragma unroll
    for (int mt = 0; mt < 2; mt++) {
        int row = wm * 32 + mt * 16 + g;
        float li0 = 1.0f / sLl[row];
        float li1 = 1.0f / sLl[row + 8];
        int q  = q0 + row;
#pragma unroll
        for (int nt = 0; nt < 4; nt++) {
            int col = wn * 32 + nt * 8 + 2 * t4;
            if (q < FF) {
                size_t gg = base + (size_t)q * EE + col;
                *(float2*)&Outr[gg] = make_float2(accR[mt][nt][0] * li0, accR[mt][nt][1] * li0);
                *(float2*)&Outi[gg] = make_float2(accI[mt][nt][0] * li0, accI[mt][nt][1] * li0);
            }
            if (q + 8 < FF) {
                size_t gg = base + (size_t)(q + 8) * EE + col;
                *(float2*)&Outr[gg] = make_float2(accR[mt][nt][2] * li1, accR[mt][nt][3] * li1);
                *(float2*)&Outi[gg] = make_float2(accI[mt][nt][2] * li1, accI[mt][nt][3] * li1);
            }
        }
    }
}

// ---------------- host launcher ----------------
extern "C" void kernel_launch(void* const* d_in, const int* in_sizes, int n_in,
                              void* d_out, int out_size)
{
    const float* x    = (const float*)d_in[0];
    const float* gam  = (const float*)d_in[1];
    const float* bet  = (const float*)d_in[2];
    const float* Wq_r = (const float*)d_in[3];
    const float* bq_r = (const float*)d_in[4];
    const float* Wq_i = (const float*)d_in[5];
    const float* bq_i = (const float*)d_in[6];
    const float* Wk_r = (const float*)d_in[7];
    const float* bk_r = (const float*)d_in[8];
    const float* Wk_i = (const float*)d_in[9];
    const float* bk_i = (const float*)d_in[10];
    const float* Wv_r = (const float*)d_in[11];
    const float* bv_r = (const float*)d_in[12];
    const float* Wv_i = (const float*)d_in[13];
    const float* bv_i = (const float*)d_in[14];
    const float* Wo   = (const float*)d_in[15];
    float* out = (float*)d_out;

    static int attr_set = 0;
    if (!attr_set) {
        cudaFuncSetAttribute(attn_tc, cudaFuncAttributeMaxDynamicSharedMemorySize, ATTN_SMEM);
        attr_set = 1;
    }

    float *p_xr, *p_xi, *p_Qr, *p_Qi, *p_Kr, *p_Ki, *p_Vr, *p_Vi, *p_Or, *p_Oi, *p_y;
    cudaGetSymbolAddress((void**)&p_xr, g_xr);
    cudaGetSymbolAddress((void**)&p_xi, g_xi);
    cudaGetSymbolAddress((void**)&p_Qr, g_Qr);
    cudaGetSymbolAddress((void**)&p_Qi, g_Qi);
    cudaGetSymbolAddress((void**)&p_Kr, g_Kr);
    cudaGetSymbolAddress((void**)&p_Ki, g_Ki);
    cudaGetSymbolAddress((void**)&p_Vr, g_Vr);
    cudaGetSymbolAddress((void**)&p_Vi, g_Vi);
    cudaGetSymbolAddress((void**)&p_Or, g_Or);
    cudaGetSymbolAddress((void**)&p_Oi, g_Oi);
    cudaGetSymbolAddress((void**)&p_y,  g_y);

    const int MF = BB * FF;      // 8196
    const int ML = BB * LL;      // 16384

    twiddle_init<<<9, 256>>>();
    ln_kernel<<<BB * LL, 256>>>(x, gam, bet);
    {
        dim3 g(EE / 32, LL / 32, BB), blk(32, 8);
        transpose_LE_to_EL<<<g, blk>>>();
    }
    rfft_kernel<<<BB * EE, 256>>>();
    {
        GemmBatch gb;
        gb.g[0] = { p_xr, Wq_r, bq_r, p_Qr };
        gb.g[1] = { p_xi, Wq_i, bq_i, p_Qi };
        gb.g[2] = { p_xr, Wk_r, bk_r, p_Kr };
        gb.g[3] = { p_xi, Wk_i, bk_i, p_Ki };
        gb.g[4] = { p_xr, Wv_r, bv_r, p_Vr };
        gb.g[5] = { p_xi, Wv_i, bv_i, p_Vi };
        dim3 g((MF + 127) / 128, 8, 6);
        gemm_tc<<<g, 256>>>(gb, MF);
    }
    {
        dim3 g((FF + 127) / 128, BB * HH);
        attn_tc<<<g, 256, ATTN_SMEM>>>(p_Qr, p_Qi, p_Kr, p_Ki, p_Vr, p_Vi, p_Or, p_Oi);
    }
    irfft_kernel<<<BB * EE, 256>>>();
    {
        dim3 g(LL / 32, EE / 32, BB), blk(32, 8);
        transpose_EL_to_LE<<<g, blk>>>();
    }
    {
        GemmBatch gb;
        gb.g[0] = { p_y, Wo, nullptr, out };
        gb.g[1] = gb.g[0]; gb.g[2] = gb.g[0]; gb.g[3] = gb.g[0];
        gb.g[4] = gb.g[0]; gb.g[5] = gb.g[0];
        dim3 g((ML + 127) / 128, 8, 1);
        gemm_tc<<<g, 256>>>(gb, ML);
    }
}

// round 12
// speedup vs baseline: 1.8020x; 1.4590x over previous
#include <cuda_runtime.h>
#include <math.h>
#include <stdint.h>

// ---------------- problem constants ----------------
#define BB 4
#define LL 4096
#define EE 512
#define FF 2049
#define FFP 2064           // padded F (16-float multiple) for transposed V
#define HH 8
#define DD 64
#define FFTM 2048          // half-size complex FFT length

// ---------------- scratch (device globals; allocation-free) ----------------
__device__ float g_xn[BB * LL * EE];
__device__ float g_xt[BB * EE * LL];
__device__ float g_xr[BB * FF * EE];
__device__ float g_xi[BB * FF * EE];
__device__ float g_Qr[BB * FF * EE];
__device__ float g_Qi[BB * FF * EE];
__device__ float g_Kr[BB * FF * EE];
__device__ float g_Ki[BB * FF * EE];
__device__ float g_VtR[BB * HH * DD * FFP];   // V real, transposed [b][h][d][FFP]
__device__ float g_VtI[BB * HH * DD * FFP];
__device__ float g_Or[BB * FF * EE];
__device__ float g_Oi[BB * FF * EE];
__device__ float g_y [BB * LL * EE];
__device__ float2 g_twS[1024];
__device__ float2 g_twP[FF];

// ---------------- helpers ----------------
__device__ __forceinline__ float tf32r(float x) {
    unsigned u;
    asm("cvt.rna.tf32.f32 %0, %1;" : "=r"(u) : "f"(x));
    return __uint_as_float(u);
}
__device__ __forceinline__ void mma8(float* c, const float* a, const float* b) {
    asm volatile(
        "mma.sync.aligned.m16n8k8.row.col.f32.tf32.tf32.f32 "
        "{%0,%1,%2,%3},{%4,%5,%6,%7},{%8,%9},{%0,%1,%2,%3};"
        : "+f"(c[0]), "+f"(c[1]), "+f"(c[2]), "+f"(c[3])
        : "r"(__float_as_uint(a[0])), "r"(__float_as_uint(a[1])),
          "r"(__float_as_uint(a[2])), "r"(__float_as_uint(a[3])),
          "r"(__float_as_uint(b[0])), "r"(__float_as_uint(b[1])));
}
__device__ __forceinline__ uint32_t smem_u32(const void* p) {
    uint32_t a;
    asm("{ .reg .u64 t; cvta.to.shared.u64 t, %1; cvt.u32.u64 %0, t; }" : "=r"(a) : "l"(p));
    return a;
}
__device__ __forceinline__ void cpa16(uint32_t dst, const void* src, uint32_t bytes) {
    asm volatile("cp.async.cg.shared.global [%0], [%1], 16, %2;"
                 :: "r"(dst), "l"(src), "r"(bytes) : "memory");
}
#define CP_COMMIT()  asm volatile("cp.async.commit_group;" ::: "memory")
#define CP_WAITALL() asm volatile("cp.async.wait_all;" ::: "memory")

// ---------------- twiddle table init ----------------
__global__ void twiddle_init()
{
    int t = blockIdx.x * 256 + threadIdx.x;
    if (t < 1024) {
        float sn, cs; sincospif(-(float)t * (1.0f / 1024.0f), &sn, &cs);
        g_twS[t] = make_float2(cs, sn);
    }
    if (t < FF) {
        float sn, cs; sincospif(-(float)t * (1.0f / 2048.0f), &sn, &cs);
        g_twP[t] = make_float2(cs, sn);
    }
}

// ---------------- LayerNorm ----------------
__global__ void ln_kernel(const float* __restrict__ x,
                          const float* __restrict__ gam,
                          const float* __restrict__ bet)
{
    __shared__ float sa[8], sb[8];
    int row = blockIdx.x;
    const float* xr = x + (size_t)row * EE;
    float* o = g_xn + (size_t)row * EE;
    int t = threadIdx.x;
    float v0 = xr[t], v1 = xr[t + 256];
    float s = v0 + v1, s2 = v0 * v0 + v1 * v1;
#pragma unroll
    for (int off = 16; off; off >>= 1) {
        s  += __shfl_xor_sync(0xffffffffu, s,  off);
        s2 += __shfl_xor_sync(0xffffffffu, s2, off);
    }
    if ((t & 31) == 0) { sa[t >> 5] = s; sb[t >> 5] = s2; }
    __syncthreads();
    s = 0.f; s2 = 0.f;
#pragma unroll
    for (int i = 0; i < 8; i++) { s += sa[i]; s2 += sb[i]; }
    float mean = s * (1.0f / EE);
    float var  = s2 * (1.0f / EE) - mean * mean;
    float rs   = rsqrtf(var + 1e-5f);
    o[t]       = (v0 - mean) * rs * gam[t]       + bet[t];
    o[t + 256] = (v1 - mean) * rs * gam[t + 256] + bet[t + 256];
}

// ---------------- transposes ----------------
__global__ void transpose_LE_to_EL()
{
    __shared__ float tile[32][33];
    int b  = blockIdx.z;
    int e0 = blockIdx.x * 32;
    int l0 = blockIdx.y * 32;
    const float* s = g_xn + ((size_t)b * LL + l0) * EE + e0;
    for (int rr = threadIdx.y; rr < 32; rr += 8)
        tile[rr][threadIdx.x] = s[(size_t)rr * EE + threadIdx.x];
    __syncthreads();
    float* d = g_xt + ((size_t)b * EE + e0) * LL + l0;
    for (int rr = threadIdx.y; rr < 32; rr += 8)
        d[(size_t)rr * LL + threadIdx.x] = tile[threadIdx.x][rr];
}

__global__ void transpose_EL_to_LE()
{
    __shared__ float tile[32][33];
    int b  = blockIdx.z;
    int l0 = blockIdx.x * 32;
    int e0 = blockIdx.y * 32;
    const float* s = g_xt + ((size_t)b * EE + e0) * LL + l0;
    for (int rr = threadIdx.y; rr < 32; rr += 8)
        tile[rr][threadIdx.x] = s[(size_t)rr * LL + threadIdx.x];
    __syncthreads();
    float* d = g_y + ((size_t)b * LL + l0) * EE + e0;
    for (int rr = threadIdx.y; rr < 32; rr += 8)
        d[(size_t)rr * EE + threadIdx.x] = tile[threadIdx.x][rr];
}

// ---------------- Stockham FFT (complex, length 2048, 256 threads) ----------------
__device__ __forceinline__ float2* fft_stockham2048(float2* src, float2* dst,
                                                    const float2* __restrict__ tw, int t)
{
#pragma unroll 1
    for (int stage = 0; stage < 11; stage++) {
        int s = 1 << stage;
#pragma unroll
        for (int i = 0; i < 4; i++) {
            int j = t + (i << 8);
            int p = j >> stage;
            int q = j & (s - 1);
            float2 u = src[q + (p << stage)];
            float2 v = src[q + ((p + (1024 >> stage)) << stage)];
            float2 ss = make_float2(u.x + v.x, u.y + v.y);
            float2 dd = make_float2(u.x - v.x, u.y - v.y);
            float2 w  = tw[p << stage];
            int od = q + (p << (stage + 1));
            dst[od]     = ss;
            dst[od + s] = make_float2(dd.x * w.x - dd.y * w.y,
                                      dd.x * w.y + dd.y * w.x);
        }
        __syncthreads();
        float2* tmp = src; src = dst; dst = tmp;
    }
    return src;
}

__global__ void rfft_kernel()
{
    __shared__ float2 bufA[FFTM], bufB[FFTM];
    __shared__ float2 tw[1024];
    int t  = threadIdx.x;
    int be = blockIdx.x;
    int b  = be >> 9, e = be & 511;

    const float2* src = (const float2*)(g_xt + (size_t)be * LL);
#pragma unroll
    for (int i = 0; i < 8; i++) bufA[t + (i << 8)] = src[t + (i << 8)];
#pragma unroll
    for (int i = 0; i < 4; i++) tw[t + (i << 8)] = g_twS[t + (i << 8)];
    __syncthreads();
    float2* Z = fft_stockham2048(bufA, bufB, tw, t);

    const float scale = 1.0f / 64.0f;
    for (int k = t; k <= FFTM; k += 256) {
        float2 zk = Z[k & (FFTM - 1)];
        float2 zm = Z[(FFTM - k) & (FFTM - 1)];
        float Er  = 0.5f * (zk.x + zm.x);
        float Eii = 0.5f * (zk.y - zm.y);
        float Or0 = 0.5f * (zk.x - zm.x);
        float Oi0 = 0.5f * (zk.y + zm.y);
        float2 w = g_twP[k];
        float ux = w.x * Or0 - w.y * Oi0;
        float uy = w.x * Oi0 + w.y * Or0;
        size_t g = ((size_t)b * FF + k) * EE + e;
        g_xr[g] = (Er  + uy) * scale;
        g_xi[g] = (Eii - ux) * scale;
    }
}

__global__ void irfft_kernel()
{
    __shared__ float2 bufA[FFTM], bufB[FFTM];
    __shared__ float2 tw[1024];
    int t  = threadIdx.x;
    int be = blockIdx.x;
    int b  = be >> 9, e = be & 511;

#pragma unroll
    for (int i = 0; i < 4; i++) {
        float2 w = g_twS[t + (i << 8)];
        tw[t + (i << 8)] = make_float2(w.x, -w.y);
    }
    for (int k = t; k < FFTM; k += 256) {
        size_t gk = ((size_t)b * FF + k) * EE + e;
        size_t gm = ((size_t)b * FF + (FFTM - k)) * EE + e;
        float Xr_k = g_Or[gk];
        float Xi_k = (k == 0) ? 0.0f : g_Oi[gk];
        float Xr_m = g_Or[gm];
        float Xi_m = (k == 0) ? 0.0f : g_Oi[gm];
        float Er  = 0.5f * (Xr_k + Xr_m);
        float Ei  = 0.5f * (Xi_k - Xi_m);
        float Or0 = 0.5f * (Xr_k - Xr_m);
        float Oi0 = 0.5f * (Xi_k + Xi_m);
        float2 w = g_twP[k];
        float cs = w.x, sn = -w.y;
        float ux = cs * Or0 - sn * Oi0;
        float uy = cs * Oi0 + sn * Or0;
        bufA[k] = make_float2(Er - uy, Ei + ux);
    }
    __syncthreads();
    float2* w = fft_stockham2048(bufA, bufB, tw, t);

    float2* out = (float2*)(g_xt + (size_t)be * LL);
    const float sc = 1.0f / 32.0f;
#pragma unroll
    for (int i = 0; i < 8; i++) {
        int n = t + (i << 8);
        float2 z = w[n];
        out[n] = make_float2(z.x * sc, z.y * sc);
    }
}

// ---------------- tf32 tensor-core GEMM (mma.sync), batched over grid.z ----------------
// mode 0: plain fp32 out.  mode 1: tf32-rounded out.  mode 2: tf32-rounded, transposed V out.
struct GemmPtrs { const float *A, *W, *bias; float *C; int mode; };
struct GemmBatch { GemmPtrs g[6]; };

__global__ void __launch_bounds__(256) gemm_tc(GemmBatch batch, int M)
{
    __shared__ float sA[128 * 36];
    __shared__ float sB[64 * 36];
    GemmPtrs gp = batch.g[blockIdx.z];
    int m0 = blockIdx.x * 128, n0 = blockIdx.y * 64;
    int t = threadIdx.x, lane = t & 31, w = t >> 5;
    int g = lane >> 2, t4 = lane & 3;
    int wm = w >> 1, wn = w & 1;
    float acc[2][4][4] = {};

    for (int k0 = 0; k0 < 512; k0 += 32) {
#pragma unroll
        for (int i = 0; i < 4; i++) {
            int id = t + i * 256;
            int r = id >> 3, kq = (id & 7) * 4;
            float4 v = make_float4(0.f, 0.f, 0.f, 0.f);
            if (m0 + r < M) v = *(const float4*)&gp.A[(size_t)(m0 + r) * 512 + k0 + kq];
            float* d = &sA[r * 36 + kq];
            d[0] = tf32r(v.x); d[1] = tf32r(v.y); d[2] = tf32r(v.z); d[3] = tf32r(v.w);
        }
#pragma unroll
        for (int i = 0; i < 2; i++) {
            int id = t + i * 256;
            int r = id >> 3, kq = (id & 7) * 4;
            float4 v = *(const float4*)&gp.W[(size_t)(n0 + r) * 512 + k0 + kq];
            float* d = &sB[r * 36 + kq];
            d[0] = tf32r(v.x); d[1] = tf32r(v.y); d[2] = tf32r(v.z); d[3] = tf32r(v.w);
        }
        __syncthreads();
#pragma unroll
        for (int ks = 0; ks < 4; ks++) {
            int kk = ks * 8 + t4;
            float a[2][4];
#pragma unroll
            for (int mt = 0; mt < 2; mt++) {
                int row = wm * 32 + mt * 16 + g;
                a[mt][0] = sA[row * 36 + kk];
                a[mt][1] = sA[(row + 8) * 36 + kk];
                a[mt][2] = sA[row * 36 + kk + 4];
                a[mt][3] = sA[(row + 8) * 36 + kk + 4];
            }
#pragma unroll
            for (int nt = 0; nt < 4; nt++) {
                int col = wn * 32 + nt * 8 + g;
                float b[2] = { sB[col * 36 + kk], sB[col * 36 + kk + 4] };
                mma8(acc[0][nt], a[0], b);
                mma8(acc[1][nt], a[1], b);
            }
        }
        __syncthreads();
    }
#pragma unroll
    for (int nt = 0; nt < 4; nt++) {
        int col = n0 + wn * 32 + nt * 8 + 2 * t4;
        float b0 = gp.bias ? gp.bias[col] : 0.f;
        float b1 = gp.bias ? gp.bias[col + 1] : 0.f;
#pragma unroll
        for (int mt = 0; mt < 2; mt++) {
#pragma unroll
            for (int half = 0; half < 2; half++) {
                int row = m0 + wm * 32 + mt * 16 + half * 8 + g;
                if (row >= M) continue;
                float v0 = acc[mt][nt][half * 2 + 0] + b0;
                float v1 = acc[mt][nt][half * 2 + 1] + b1;
                if (gp.mode == 2) {
                    int bb = row / FF, f = row - bb * FF;
                    int hh = col >> 6, dd = col & 63;
                    size_t gbase = ((size_t)((bb * 8 + hh) * 64 + dd)) * FFP + f;
                    gp.C[gbase]       = tf32r(v0);
                    gp.C[gbase + FFP] = tf32r(v1);   // col+1 -> d+1
                } else {
                    if (gp.mode == 1) { v0 = tf32r(v0); v1 = tf32r(v1); }
                    *(float2*)&gp.C[(size_t)row * 512 + col] = make_float2(v0, v1);
                }
            }
        }
    }
}

// ---------------- tf32 flash attention with cp.async prefetch ----------------
// q-tile 128, k-tile 64. K double-buffered, V (pre-transposed) single-buffered.
// smem floats: Q 2*8704 | K 2 bufs * 2 * 4352 | V 2*4352 | S 8704 | stats 384 = 52608 (210.4 KB)
#define SQ_LD 68
#define OFF_Q   0
#define OFF_K0  17408
#define OFF_K1  26112
#define OFF_V   34816
#define OFF_S   43520
#define OFF_ST  52224
#define ATTN_SMEM (52608 * 4)
__global__ void __launch_bounds__(256, 1) attn_tc(
    const float* __restrict__ Qr, const float* __restrict__ Qi,
    const float* __restrict__ Kr, const float* __restrict__ Ki,
    float* __restrict__ Outr, float* __restrict__ Outi)
{
    extern __shared__ float sm[];
    float* sQr = sm + OFF_Q;
    float* sQi = sQr + 8704;
    float* sS  = sm + OFF_S;
    float* sMm = sm + OFF_ST;
    float* sLl = sMm + 128;
    float* sAl = sLl + 128;

    int bh = blockIdx.y;
    int b = bh >> 3, h = bh & 7;
    int q0 = blockIdx.x * 128;
    int t = threadIdx.x, lane = t & 31, w = t >> 5;
    int g = lane >> 2, t4 = lane & 3;
    int wm = w >> 1, wn = w & 1;
    const size_t base = (size_t)b * FF * EE + h * DD;
    const size_t vtbase = (size_t)(bh * 64) * FFP;

    uint32_t sb = smem_u32(sm);
    uint32_t aK[2] = { sb + OFF_K0 * 4u, sb + OFF_K1 * 4u };
    uint32_t aV = sb + OFF_V * 4u;

    // ---- K-tile prefetch: 2048 16B chunks (r+i), 8 per thread ----
    auto issueK = [&](int kt, int p) {
#pragma unroll
        for (int j = 0; j < 8; j++) {
            int idx = t + j * 256;
            int comp = idx >> 10;
            int rem = idx & 1023;
            int f = rem >> 4, c = rem & 15;
            int gf = kt * 64 + f;
            const float* srcb = comp ? Ki : Kr;
            const float* src = srcb;
            uint32_t bytes = 0;
            if (gf < FF) { src = srcb + base + (size_t)gf * EE + c * 4; bytes = 16; }
            cpa16(aK[p] + (uint32_t)(comp * 4352 + f * SQ_LD + c * 4) * 4u, src, bytes);
        }
    };
    // ---- V-tile prefetch: rows d, contiguous f (pre-transposed global) ----
    auto issueV = [&](int f0) {
#pragma unroll
        for (int j = 0; j < 8; j++) {
            int idx = t + j * 256;
            int comp = idx >> 10;
            int rem = idx & 1023;
            int d = rem >> 4, c = rem & 15;
            int fb = f0 + c * 4;
            const float* srcb = comp ? g_VtI : g_VtR;
            const float* src = srcb;
            uint32_t bytes = 0;
            if (fb < FF) {
                src = srcb + vtbase + (size_t)d * FFP + fb;
                bytes = (fb + 4 <= FF) ? 16u : (uint32_t)(FF - fb) * 4u;
            }
            cpa16(aV + (uint32_t)(comp * 4352 + d * SQ_LD + c * 4) * 4u, src, bytes);
        }
    };

    // preload K tile 0; load Q (pre-rounded tf32; *0.125 is exact)
    issueK(0, 0);
    CP_COMMIT();
    if (t < 128) { sMm[t] = -1e30f; sLl[t] = 0.f; }
    for (int idx = t; idx < 8192; idx += 256) {
        int q = idx >> 6, d = idx & 63;
        int gq = q0 + q;
        float vr = 0.f, vi = 0.f;
        if (gq < FF) {
            size_t gg = base + (size_t)gq * EE + d;
            vr = Qr[gg] * 0.125f; vi = Qi[gg] * 0.125f;
        }
        sQr[q * SQ_LD + d] = vr;
        sQi[q * SQ_LD + d] = vi;
    }
    CP_WAITALL();

    float accR[2][4][4] = {}, accI[2][4][4] = {};

    for (int it = 0; it < 33; it++) {
        int p = it & 1;
        int f0 = it * 64;
        __syncthreads();                       // K[p],Q visible; prev PV done with V,S; prev S done with K[p^1]
        if (it < 32) issueK(it + 1, p ^ 1);
        issueV(f0);
        CP_COMMIT();

        float* sKr = sm + (p ? OFF_K1 : OFF_K0);
        float* sKi = sKr + 4352;

        // S = Qr Kr^T + Qi Ki^T
        float sacc[2][4][4] = {};
#pragma unroll
        for (int ks = 0; ks < 8; ks++) {
            int kk = ks * 8 + t4;
            float a[2][4];
#pragma unroll
            for (int mt = 0; mt < 2; mt++) {
                int row = wm * 32 + mt * 16 + g;
                a[mt][0] = sQr[row * SQ_LD + kk];
                a[mt][1] = sQr[(row + 8) * SQ_LD + kk];
                a[mt][2] = sQr[row * SQ_LD + kk + 4];
                a[mt][3] = sQr[(row + 8) * SQ_LD + kk + 4];
            }
#pragma unroll
            for (int nt = 0; nt < 4; nt++) {
                int f = wn * 32 + nt * 8 + g;
                float bfr[2] = { sKr[f * SQ_LD + kk], sKr[f * SQ_LD + kk + 4] };
                mma8(sacc[0][nt], a[0], bfr);
                mma8(sacc[1][nt], a[1], bfr);
            }
        }
#pragma unroll
        for (int ks = 0; ks < 8; ks++) {
            int kk = ks * 8 + t4;
            float a[2][4];
#pragma unroll
            for (int mt = 0; mt < 2; mt++) {
                int row = wm * 32 + mt * 16 + g;
                a[mt][0] = sQi[row * SQ_LD + kk];
                a[mt][1] = sQi[(row + 8) * SQ_LD + kk];
                a[mt][2] = sQi[row * SQ_LD + kk + 4];
                a[mt][3] = sQi[(row + 8) * SQ_LD + kk + 4];
            }
#pragma unroll
            for (int nt = 0; nt < 4; nt++) {
                int f = wn * 32 + nt * 8 + g;
                float bfi[2] = { sKi[f * SQ_LD + kk], sKi[f * SQ_LD + kk + 4] };
                mma8(sacc[0][nt], a[0], bfi);
                mma8(sacc[1][nt], a[1], bfi);
            }
        }
#pragma unroll
        for (int mt = 0; mt < 2; mt++) {
            int row = wm * 32 + mt * 16 + g;
#pragma unroll
            for (int nt = 0; nt < 4; nt++) {
                int col = wn * 32 + nt * 8 + 2 * t4;
                *(float2*)&sS[row * SQ_LD + col]       = make_float2(sacc[mt][nt][0], sacc[mt][nt][1]);
                *(float2*)&sS[(row + 8) * SQ_LD + col] = make_float2(sacc[mt][nt][2], sacc[mt][nt][3]);
            }
        }
        __syncthreads();

        // softmax: 2 threads per row, 32 cols each
        {
            int r = t >> 1, c0 = (t & 1) * 32;
            float4 v[8];
            float mx = -1e30f;
#pragma unroll
            for (int j = 0; j < 8; j++) {
                v[j] = *(float4*)&sS[r * SQ_LD + c0 + j * 4];
                int cb = f0 + c0 + j * 4;
                if (cb + 0 < FF) mx = fmaxf(mx, v[j].x);
                if (cb + 1 < FF) mx = fmaxf(mx, v[j].y);
                if (cb + 2 < FF) mx = fmaxf(mx, v[j].z);
                if (cb + 3 < FF) mx = fmaxf(mx, v[j].w);
            }
            mx = fmaxf(mx, __shfl_xor_sync(0xffffffffu, mx, 1));
            float mold = sMm[r];
            float mnew = fmaxf(mold, mx);
            float al = __expf(mold - mnew);
            float sum = 0.f;
#pragma unroll
            for (int j = 0; j < 8; j++) {
                int cb = f0 + c0 + j * 4;
                float p0 = (cb + 0 < FF) ? __expf(v[j].x - mnew) : 0.f;
                float p1 = (cb + 1 < FF) ? __expf(v[j].y - mnew) : 0.f;
                float p2 = (cb + 2 < FF) ? __expf(v[j].z - mnew) : 0.f;
                float p3 = (cb + 3 < FF) ? __expf(v[j].w - mnew) : 0.f;
                sum += p0 + p1 + p2 + p3;
                v[j] = make_float4(tf32r(p0), tf32r(p1), tf32r(p2), tf32r(p3));
            }
            sum += __shfl_xor_sync(0xffffffffu, sum, 1);
            if ((t & 1) == 0) {
                sMm[r] = mnew;
                sLl[r] = sLl[r] * al + sum;
                sAl[r] = al;
            }
#pragma unroll
            for (int j = 0; j < 8; j++)
                *(float4*)&sS[r * SQ_LD + c0 + j * 4] = v[j];
        }
        __syncthreads();

        // rescale accumulators (overlaps with V arrival)
#pragma unroll
        for (int mt = 0; mt < 2; mt++) {
            int row = wm * 32 + mt * 16 + g;
            float a0 = sAl[row], a1 = sAl[row + 8];
#pragma unroll
            for (int nt = 0; nt < 4; nt++) {
                accR[mt][nt][0] *= a0; accR[mt][nt][1] *= a0;
                accR[mt][nt][2] *= a1; accR[mt][nt][3] *= a1;
                accI[mt][nt][0] *= a0; accI[mt][nt][1] *= a0;
                accI[mt][nt][2] *= a1; accI[mt][nt][3] *= a1;
            }
        }
        CP_WAITALL();
        __syncthreads();

        // O += P @ V   (V resident as [d][f])
        float* sVr = sm + OFF_V;
        float* sVi = sVr + 4352;
#pragma unroll
        for (int ks = 0; ks < 8; ks++) {
            int kk = ks * 8 + t4;
            float a[2][4];
#pragma unroll
            for (int mt = 0; mt < 2; mt++) {
                int row = wm * 32 + mt * 16 + g;
                a[mt][0] = sS[row * SQ_LD + kk];
                a[mt][1] = sS[(row + 8) * SQ_LD + kk];
                a[mt][2] = sS[row * SQ_LD + kk + 4];
                a[mt][3] = sS[(row + 8) * SQ_LD + kk + 4];
            }
#pragma unroll
            for (int nt = 0; nt < 4; nt++) {
                int dd = wn * 32 + nt * 8 + g;
                float br[2] = { sVr[dd * SQ_LD + kk], sVr[dd * SQ_LD + kk + 4] };
                mma8(accR[0][nt], a[0], br);
                mma8(accR[1][nt], a[1], br);
                float bi[2] = { sVi[dd * SQ_LD + kk], sVi[dd * SQ_LD + kk + 4] };
                mma8(accI[0][nt], a[0], bi);
                mma8(accI[1][nt], a[1], bi);
            }
        }
    }
    __syncthreads();

    // write output (divide by l)
#pragma unroll
    for (int mt = 0; mt < 2; mt++) {
        int row = wm * 32 + mt * 16 + g;
        float li0 = 1.0f / sLl[row];
        float li1 = 1.0f / sLl[row + 8];
        int q  = q0 + row;
#pragma unroll
        for (int nt = 0; nt < 4; nt++) {
            int col = wn * 32 + nt * 8 + 2 * t4;
            if (q < FF) {
                size_t gg = base + (size_t)q * EE + col;
                *(float2*)&Outr[gg] = make_float2(accR[mt][nt][0] * li0, accR[mt][nt][1] * li0);
                *(float2*)&Outi[gg] = make_float2(accI[mt][nt][0] * li0, accI[mt][nt][1] * li0);
            }
            if (q + 8 < FF) {
                size_t gg = base + (size_t)(q + 8) * EE + col;
                *(float2*)&Outr[gg] = make_float2(accR[mt][nt][2] * li1, accR[mt][nt][3] * li1);
                *(float2*)&Outi[gg] = make_float2(accI[mt][nt][2] * li1, accI[mt][nt][3] * li1);
            }
        }
    }
}

// ---------------- host launcher ----------------
extern "C" void kernel_launch(void* const* d_in, const int* in_sizes, int n_in,
                              void* d_out, int out_size)
{
    const float* x    = (const float*)d_in[0];
    const float* gam  = (const float*)d_in[1];
    const float* bet  = (const float*)d_in[2];
    const float* Wq_r = (const float*)d_in[3];
    const float* bq_r = (const float*)d_in[4];
    const float* Wq_i = (const float*)d_in[5];
    const float* bq_i = (const float*)d_in[6];
    const float* Wk_r = (const float*)d_in[7];
    const float* bk_r = (const float*)d_in[8];
    const float* Wk_i = (const float*)d_in[9];
    const float* bk_i = (const float*)d_in[10];
    const float* Wv_r = (const float*)d_in[11];
    const float* bv_r = (const float*)d_in[12];
    const float* Wv_i = (const float*)d_in[13];
    const float* bv_i = (const float*)d_in[14];
    const float* Wo   = (const float*)d_in[15];
    float* out = (float*)d_out;

    static int attr_set = 0;
    if (!attr_set) {
        cudaFuncSetAttribute(attn_tc, cudaFuncAttributeMaxDynamicSharedMemorySize, ATTN_SMEM);
        attr_set = 1;
    }

    float *p_xr, *p_xi, *p_Qr, *p_Qi, *p_Kr, *p_Ki, *p_VtR, *p_VtI, *p_Or, *p_Oi, *p_y;
    cudaGetSymbolAddress((void**)&p_xr, g_xr);
    cudaGetSymbolAddress((void**)&p_xi, g_xi);
    cudaGetSymbolAddress((void**)&p_Qr, g_Qr);
    cudaGetSymbolAddress((void**)&p_Qi, g_Qi);
    cudaGetSymbolAddress((void**)&p_Kr, g_Kr);
    cudaGetSymbolAddress((void**)&p_Ki, g_Ki);
    cudaGetSymbolAddress((void**)&p_VtR, g_VtR);
    cudaGetSymbolAddress((void**)&p_VtI, g_VtI);
    cudaGetSymbolAddress((void**)&p_Or, g_Or);
    cudaGetSymbolAddress((void**)&p_Oi, g_Oi);
    cudaGetSymbolAddress((void**)&p_y,  g_y);

    const int MF = BB * FF;      // 8196
    const int ML = BB * LL;      // 16384

    twiddle_init<<<9, 256>>>();
    ln_kernel<<<BB * LL, 256>>>(x, gam, bet);
    {
        dim3 g(EE / 32, LL / 32, BB), blk(32, 8);
        transpose_LE_to_EL<<<g, blk>>>();
    }
    rfft_kernel<<<BB * EE, 256>>>();
    {
        GemmBatch gb;
        gb.g[0] = { p_xr, Wq_r, bq_r, p_Qr, 1 };
        gb.g[1] = { p_xi, Wq_i, bq_i, p_Qi, 1 };
        gb.g[2] = { p_xr, Wk_r, bk_r, p_Kr, 1 };
        gb.g[3] = { p_xi, Wk_i, bk_i, p_Ki, 1 };
        gb.g[4] = { p_xr, Wv_r, bv_r, p_VtR, 2 };
        gb.g[5] = { p_xi, Wv_i, bv_i, p_VtI, 2 };
        dim3 g((MF + 127) / 128, 8, 6);
        gemm_tc<<<g, 256>>>(gb, MF);
    }
    {
        dim3 g((FF + 127) / 128, BB * HH);
        attn_tc<<<g, 256, ATTN_SMEM>>>(p_Qr, p_Qi, p_Kr, p_Ki, p_Or, p_Oi);
    }
    irfft_kernel<<<BB * EE, 256>>>();
    {
        dim3 g(LL / 32, EE / 32, BB), blk(32, 8);
        transpose_EL_to_LE<<<g, blk>>>();
    }
    {
        GemmBatch gb;
        gb.g[0] = { p_y, Wo, nullptr, out, 0 };
        gb.g[1] = gb.g[0]; gb.g[2] = gb.g[0]; gb.g[3] = gb.g[0];
        gb.g[4] = gb.g[0]; gb.g[5] = gb.g[0];
        dim3 g((ML + 127) / 128, 8, 1);
        gemm_tc<<<g, 256>>>(gb, ML);
    }
}

// round 14
// speedup vs baseline: 2.2616x; 1.2551x over previous
#include <cuda_runtime.h>
#include <cuda_fp16.h>
#include <math.h>
#include <stdint.h>

// ---------------- problem constants ----------------
#define BB 4
#define LL 4096
#define EE 512
#define FF 2049
#define FFP 2064           // padded F for transposed V
#define HH 8
#define DD 64
#define FFTM 2048

// ---------------- scratch (device globals; allocation-free) ----------------
__device__ float g_xn[BB * LL * EE];
__device__ float g_xt[BB * EE * LL];
__device__ float g_xr[BB * FF * EE];
__device__ float g_xi[BB * FF * EE];
__device__ __half g_Qhr[BB * FF * EE];
__device__ __half g_Qhi[BB * FF * EE];
__device__ __half g_Khr[BB * FF * EE];
__device__ __half g_Khi[BB * FF * EE];
__device__ __half g_VtHr[BB * HH * DD * FFP];   // V transposed [bh][d][FFP]
__device__ __half g_VtHi[BB * HH * DD * FFP];
__device__ float g_Or[BB * FF * EE];
__device__ float g_Oi[BB * FF * EE];
__device__ float g_y [BB * LL * EE];
__device__ float2 g_twS[1024];
__device__ float2 g_twP[FF];

// ---------------- helpers ----------------
__device__ __forceinline__ float tf32r(float x) {
    unsigned u;
    asm("cvt.rna.tf32.f32 %0, %1;" : "=r"(u) : "f"(x));
    return __uint_as_float(u);
}
__device__ __forceinline__ void mma8(float* c, const float* a, const float* b) {
    asm volatile(
        "mma.sync.aligned.m16n8k8.row.col.f32.tf32.tf32.f32 "
        "{%0,%1,%2,%3},{%4,%5,%6,%7},{%8,%9},{%0,%1,%2,%3};"
        : "+f"(c[0]), "+f"(c[1]), "+f"(c[2]), "+f"(c[3])
        : "r"(__float_as_uint(a[0])), "r"(__float_as_uint(a[1])),
          "r"(__float_as_uint(a[2])), "r"(__float_as_uint(a[3])),
          "r"(__float_as_uint(b[0])), "r"(__float_as_uint(b[1])));
}
__device__ __forceinline__ void mma16(float* c, const uint32_t* a, const uint32_t* b) {
    asm volatile(
        "mma.sync.aligned.m16n8k16.row.col.f32.f16.f16.f32 "
        "{%0,%1,%2,%3},{%4,%5,%6,%7},{%8,%9},{%0,%1,%2,%3};"
        : "+f"(c[0]), "+f"(c[1]), "+f"(c[2]), "+f"(c[3])
        : "r"(a[0]), "r"(a[1]), "r"(a[2]), "r"(a[3]),
          "r"(b[0]), "r"(b[1]));
}
__device__ __forceinline__ void ldsm4(uint32_t addr, uint32_t* r) {
    asm volatile("ldmatrix.sync.aligned.m8n8.x4.shared.b16 {%0,%1,%2,%3}, [%4];"
                 : "=r"(r[0]), "=r"(r[1]), "=r"(r[2]), "=r"(r[3]) : "r"(addr));
}
__device__ __forceinline__ uint32_t smem_u32(const void* p) {
    uint32_t a;
    asm("{ .reg .u64 t; cvta.to.shared.u64 t, %1; cvt.u32.u64 %0, t; }" : "=r"(a) : "l"(p));
    return a;
}
__device__ __forceinline__ void cpa16(uint32_t dst, const void* src, uint32_t bytes) {
    asm volatile("cp.async.cg.shared.global [%0], [%1], 16, %2;"
                 :: "r"(dst), "l"(src), "r"(bytes) : "memory");
}
#define CP_COMMIT()  asm volatile("cp.async.commit_group;" ::: "memory")
#define CP_WAITALL() asm volatile("cp.async.wait_all;" ::: "memory")

// ---------------- twiddle table init ----------------
__global__ void twiddle_init()
{
    int t = blockIdx.x * 256 + threadIdx.x;
    if (t < 1024) {
        float sn, cs; sincospif(-(float)t * (1.0f / 1024.0f), &sn, &cs);
        g_twS[t] = make_float2(cs, sn);
    }
    if (t < FF) {
        float sn, cs; sincospif(-(float)t * (1.0f / 2048.0f), &sn, &cs);
        g_twP[t] = make_float2(cs, sn);
    }
}

// ---------------- LayerNorm ----------------
__global__ void ln_kernel(const float* __restrict__ x,
                          const float* __restrict__ gam,
                          const float* __restrict__ bet)
{
    __shared__ float sa[8], sb[8];
    int row = blockIdx.x;
    const float* xr = x + (size_t)row * EE;
    float* o = g_xn + (size_t)row * EE;
    int t = threadIdx.x;
    float v0 = xr[t], v1 = xr[t + 256];
    float s = v0 + v1, s2 = v0 * v0 + v1 * v1;
#pragma unroll
    for (int off = 16; off; off >>= 1) {
        s  += __shfl_xor_sync(0xffffffffu, s,  off);
        s2 += __shfl_xor_sync(0xffffffffu, s2, off);
    }
    if ((t & 31) == 0) { sa[t >> 5] = s; sb[t >> 5] = s2; }
    __syncthreads();
    s = 0.f; s2 = 0.f;
#pragma unroll
    for (int i = 0; i < 8; i++) { s += sa[i]; s2 += sb[i]; }
    float mean = s * (1.0f / EE);
    float var  = s2 * (1.0f / EE) - mean * mean;
    float rs   = rsqrtf(var + 1e-5f);
    o[t]       = (v0 - mean) * rs * gam[t]       + bet[t];
    o[t + 256] = (v1 - mean) * rs * gam[t + 256] + bet[t + 256];
}

// ---------------- transposes ----------------
__global__ void transpose_LE_to_EL()
{
    __shared__ float tile[32][33];
    int b  = blockIdx.z;
    int e0 = blockIdx.x * 32;
    int l0 = blockIdx.y * 32;
    const float* s = g_xn + ((size_t)b * LL + l0) * EE + e0;
    for (int rr = threadIdx.y; rr < 32; rr += 8)
        tile[rr][threadIdx.x] = s[(size_t)rr * EE + threadIdx.x];
    __syncthreads();
    float* d = g_xt + ((size_t)b * EE + e0) * LL + l0;
    for (int rr = threadIdx.y; rr < 32; rr += 8)
        d[(size_t)rr * LL + threadIdx.x] = tile[threadIdx.x][rr];
}

__global__ void transpose_EL_to_LE()
{
    __shared__ float tile[32][33];
    int b  = blockIdx.z;
    int l0 = blockIdx.x * 32;
    int e0 = blockIdx.y * 32;
    const float* s = g_xt + ((size_t)b * EE + e0) * LL + l0;
    for (int rr = threadIdx.y; rr < 32; rr += 8)
        tile[rr][threadIdx.x] = s[(size_t)rr * LL + threadIdx.x];
    __syncthreads();
    float* d = g_y + ((size_t)b * LL + l0) * EE + e0;
    for (int rr = threadIdx.y; rr < 32; rr += 8)
        d[(size_t)rr * EE + threadIdx.x] = tile[threadIdx.x][rr];
}

// ---------------- Stockham FFT (complex, length 2048, 256 threads) ----------------
__device__ __forceinline__ float2* fft_stockham2048(float2* src, float2* dst,
                                                    const float2* __restrict__ tw, int t)
{
#pragma unroll 1
    for (int stage = 0; stage < 11; stage++) {
        int s = 1 << stage;
#pragma unroll
        for (int i = 0; i < 4; i++) {
            int j = t + (i << 8);
            int p = j >> stage;
            int q = j & (s - 1);
            float2 u = src[q + (p << stage)];
            float2 v = src[q + ((p + (1024 >> stage)) << stage)];
            float2 ss = make_float2(u.x + v.x, u.y + v.y);
            float2 dd = make_float2(u.x - v.x, u.y - v.y);
            float2 w  = tw[p << stage];
            int od = q + (p << (stage + 1));
            dst[od]     = ss;
            dst[od + s] = make_float2(dd.x * w.x - dd.y * w.y,
                                      dd.x * w.y + dd.y * w.x);
        }
        __syncthreads();
        float2* tmp = src; src = dst; dst = tmp;
    }
    return src;
}

__global__ void rfft_kernel()
{
    __shared__ float2 bufA[FFTM], bufB[FFTM];
    __shared__ float2 tw[1024];
    int t  = threadIdx.x;
    int be = blockIdx.x;
    int b  = be >> 9, e = be & 511;

    const float2* src = (const float2*)(g_xt + (size_t)be * LL);
#pragma unroll
    for (int i = 0; i < 8; i++) bufA[t + (i << 8)] = src[t + (i << 8)];
#pragma unroll
    for (int i = 0; i < 4; i++) tw[t + (i << 8)] = g_twS[t + (i << 8)];
    __syncthreads();
    float2* Z = fft_stockham2048(bufA, bufB, tw, t);

    const float scale = 1.0f / 64.0f;
    for (int k = t; k <= FFTM; k += 256) {
        float2 zk = Z[k & (FFTM - 1)];
        float2 zm = Z[(FFTM - k) & (FFTM - 1)];
        float Er  = 0.5f * (zk.x + zm.x);
        float Eii = 0.5f * (zk.y - zm.y);
        float Or0 = 0.5f * (zk.x - zm.x);
        float Oi0 = 0.5f * (zk.y + zm.y);
        float2 w = g_twP[k];
        float ux = w.x * Or0 - w.y * Oi0;
        float uy = w.x * Oi0 + w.y * Or0;
        size_t g = ((size_t)b * FF + k) * EE + e;
        g_xr[g] = (Er  + uy) * scale;
        g_xi[g] = (Eii - ux) * scale;
    }
}

__global__ void irfft_kernel()
{
    __shared__ float2 bufA[FFTM], bufB[FFTM];
    __shared__ float2 tw[1024];
    int t  = threadIdx.x;
    int be = blockIdx.x;
    int b  = be >> 9, e = be & 511;

#pragma unroll
    for (int i = 0; i < 4; i++) {
        float2 w = g_twS[t + (i << 8)];
        tw[t + (i << 8)] = make_float2(w.x, -w.y);
    }
    for (int k = t; k < FFTM; k += 256) {
        size_t gk = ((size_t)b * FF + k) * EE + e;
        size_t gm = ((size_t)b * FF + (FFTM - k)) * EE + e;
        float Xr_k = g_Or[gk];
        float Xi_k = (k == 0) ? 0.0f : g_Oi[gk];
        float Xr_m = g_Or[gm];
        float Xi_m = (k == 0) ? 0.0f : g_Oi[gm];
        float Er  = 0.5f * (Xr_k + Xr_m);
        float Ei  = 0.5f * (Xi_k - Xi_m);
        float Or0 = 0.5f * (Xr_k - Xr_m);
        float Oi0 = 0.5f * (Xi_k + Xi_m);
        float2 w = g_twP[k];
        float cs = w.x, sn = -w.y;
        float ux = cs * Or0 - sn * Oi0;
        float uy = cs * Oi0 + sn * Or0;
        bufA[k] = make_float2(Er - uy, Ei + ux);
    }
    __syncthreads();
    float2* w = fft_stockham2048(bufA, bufB, tw, t);

    float2* out = (float2*)(g_xt + (size_t)be * LL);
    const float sc = 1.0f / 32.0f;
#pragma unroll
    for (int i = 0; i < 8; i++) {
        int n = t + (i << 8);
        float2 z = w[n];
        out[n] = make_float2(z.x * sc, z.y * sc);
    }
}

// ---------------- tf32 GEMM (mma.sync), batched; epilogue modes ----------------
// mode 0: f32 out.  mode 1: half2 out (scaled).  mode 2: half transposed-V out.
struct GemmPtrs { const float *A, *W, *bias; void *C; int mode; float scale; };
struct GemmBatch { GemmPtrs g[6]; };

__global__ void __launch_bounds__(256) gemm_tc(GemmBatch batch, int M)
{
    __shared__ float sA[128 * 36];
    __shared__ float sB[64 * 36];
    GemmPtrs gp = batch.g[blockIdx.z];
    int m0 = blockIdx.x * 128, n0 = blockIdx.y * 64;
    int t = threadIdx.x, lane = t & 31, w = t >> 5;
    int g = lane >> 2, t4 = lane & 3;
    int wm = w >> 1, wn = w & 1;
    float acc[2][4][4] = {};

    for (int k0 = 0; k0 < 512; k0 += 32) {
#pragma unroll
        for (int i = 0; i < 4; i++) {
            int id = t + i * 256;
            int r = id >> 3, kq = (id & 7) * 4;
            float4 v = make_float4(0.f, 0.f, 0.f, 0.f);
            if (m0 + r < M) v = *(const float4*)&gp.A[(size_t)(m0 + r) * 512 + k0 + kq];
            float* d = &sA[r * 36 + kq];
            d[0] = tf32r(v.x); d[1] = tf32r(v.y); d[2] = tf32r(v.z); d[3] = tf32r(v.w);
        }
#pragma unroll
        for (int i = 0; i < 2; i++) {
            int id = t + i * 256;
            int r = id >> 3, kq = (id & 7) * 4;
            float4 v = *(const float4*)&gp.W[(size_t)(n0 + r) * 512 + k0 + kq];
            float* d = &sB[r * 36 + kq];
            d[0] = tf32r(v.x); d[1] = tf32r(v.y); d[2] = tf32r(v.z); d[3] = tf32r(v.w);
        }
        __syncthreads();
#pragma unroll
        for (int ks = 0; ks < 4; ks++) {
            int kk = ks * 8 + t4;
            float a[2][4];
#pragma unroll
            for (int mt = 0; mt < 2; mt++) {
                int row = wm * 32 + mt * 16 + g;
                a[mt][0] = sA[row * 36 + kk];
                a[mt][1] = sA[(row + 8) * 36 + kk];
                a[mt][2] = sA[row * 36 + kk + 4];
                a[mt][3] = sA[(row + 8) * 36 + kk + 4];
            }
#pragma unroll
            for (int nt = 0; nt < 4; nt++) {
                int col = wn * 32 + nt * 8 + g;
                float b[2] = { sB[col * 36 + kk], sB[col * 36 + kk + 4] };
                mma8(acc[0][nt], a[0], b);
                mma8(acc[1][nt], a[1], b);
            }
        }
        __syncthreads();
    }
#pragma unroll
    for (int nt = 0; nt < 4; nt++) {
        int col = n0 + wn * 32 + nt * 8 + 2 * t4;
        float b0 = gp.bias ? gp.bias[col] : 0.f;
        float b1 = gp.bias ? gp.bias[col + 1] : 0.f;
#pragma unroll
        for (int mt = 0; mt < 2; mt++) {
#pragma unroll
            for (int half = 0; half < 2; half++) {
                int row = m0 + wm * 32 + mt * 16 + half * 8 + g;
                if (row >= M) continue;
                float v0 = acc[mt][nt][half * 2 + 0] + b0;
                float v1 = acc[mt][nt][half * 2 + 1] + b1;
                if (gp.mode == 0) {
                    *(float2*)((float*)gp.C + (size_t)row * 512 + col) = make_float2(v0, v1);
                } else if (gp.mode == 1) {
                    __half2 hv = __floats2half2_rn(v0 * gp.scale, v1 * gp.scale);
                    *(__half2*)((__half*)gp.C + (size_t)row * 512 + col) = hv;
                } else {
                    int bb = row / FF, f = row - bb * FF;
                    int hh = col >> 6, dd = col & 63;
                    __half* vh = (__half*)gp.C;
                    size_t gbase = ((size_t)((bb * 8 + hh) * 64 + dd)) * FFP + f;
                    vh[gbase]       = __float2half_rn(v0);
                    vh[gbase + FFP] = __float2half_rn(v1);
                }
            }
        }
    }
}

// ---------------- fp16 flash attention (ldmatrix + m16n8k16, register softmax) ----------------
// smem bytes: Qr 18432 | Qi 18432 | K0 18432 | K1 18432 | V 18432 | P 18432 | stats 2048
#define OQR 0
#define OQI 18432
#define OK0 36864
#define OK1 55296
#define OV  73728
#define OP  92160
#define OST 110592
#define ATTN_SMEM 112640
__global__ void __launch_bounds__(256) attn_tc(
    const __half* __restrict__ Qhr, const __half* __restrict__ Qhi,
    const __half* __restrict__ Khr, const __half* __restrict__ Khi,
    float* __restrict__ Outr, float* __restrict__ Outi)
{
    extern __shared__ char smc[];
    __half* sQ  = (__half*)smc;
    __half* sP  = (__half*)(smc + OP);
    float* sWmax = (float*)(smc + OST);          // [128][2]
    float* sWsum = sWmax + 256;                   // [128][2]

    int bh = blockIdx.y;
    int b = bh >> 3, h = bh & 7;
    int q0 = blockIdx.x * 128;
    int t = threadIdx.x, lane = t & 31, w = t >> 5;
    int g = lane >> 2, tg = lane & 3;
    int wm = w >> 1, wn = w & 1;
    const size_t baseF = (size_t)b * FF * EE + h * DD;   // f32 out base
    const size_t baseH = (size_t)(b * FF) * 512 + h * 64; // half in base (elements)

    uint32_t sb = smem_u32(smc);
    uint32_t aK[2] = { sb + OK0, sb + OK1 };
    uint32_t aV = sb + OV;

    // ldmatrix per-lane offset (16x16 tiles, ld=72 halves)
    int lrow = (lane & 7) + ((lane >> 3) & 1) * 8;
    int lcol = (lane >> 4) * 8;
    uint32_t lofs2 = (uint32_t)(lrow * 72 + lcol) * 2u;

    // ---- K prefetch: 1024 chunks of 16B (2 comp x 64 rows x 8) ----
    auto issueK = [&](int kt, int p) {
#pragma unroll
        for (int j = 0; j < 4; j++) {
            int idx = t + j * 256;
            int comp = idx >> 9;
            int rem = idx & 511;
            int f = rem >> 3, c = rem & 7;
            int gf = kt * 64 + f;
            const __half* srcb = comp ? Khi : Khr;
            const __half* src = srcb;
            uint32_t bytes = 0;
            if (gf < FF) { src = srcb + baseH + (size_t)gf * 512 + c * 8; bytes = 16; }
            cpa16(aK[p] + (uint32_t)(comp * 4608 + f * 72 + c * 8) * 2u, src, bytes);
        }
    };
    // ---- V prefetch ----
    auto issueV = [&](int f0) {
#pragma unroll
        for (int j = 0; j < 4; j++) {
            int idx = t + j * 256;
            int comp = idx >> 9;
            int rem = idx & 511;
            int d = rem >> 3, c = rem & 7;
            int fb = f0 + c * 8;
            const __half* srcb = comp ? g_VtHi : g_VtHr;
            const __half* src = srcb;
            uint32_t bytes = 0;
            if (fb < FF) {
                src = srcb + (size_t)(bh * 64 + d) * FFP + fb;
                bytes = (fb + 8 <= FF) ? 16u : (uint32_t)(FF - fb) * 2u;
            }
            cpa16(aV + (uint32_t)(comp * 4608 + d * 72 + c * 8) * 2u, src, bytes);
        }
    };

    issueK(0, 0);
    CP_COMMIT();

    // load Q tiles (pre-scaled fp16)
    __half* sQr = sQ;
    __half* sQi = (__half*)(smc + OQI);
    for (int idx = t; idx < 4096; idx += 256) {
        int q = idx >> 5, c = idx & 31;
        int gq = q0 + q;
        __half2 vr = __floats2half2_rn(0.f, 0.f), vi = vr;
        if (gq < FF) {
            vr = *(const __half2*)(Qhr + baseH + (size_t)gq * 512 + 2 * c);
            vi = *(const __half2*)(Qhi + baseH + (size_t)gq * 512 + 2 * c);
        }
        *(__half2*)(sQr + q * 72 + 2 * c) = vr;
        *(__half2*)(sQi + q * 72 + 2 * c) = vi;
    }
    CP_WAITALL();

    float accR[2][4][4] = {}, accI[2][4][4] = {};
    float m_run[2][2] = { {-1e30f, -1e30f}, {-1e30f, -1e30f} };
    float l_run[2][2] = {};

    for (int it = 0; it < 33; it++) {
        int p = it & 1;
        int f0 = it * 64;
        __syncthreads();
        if (it < 32) issueK(it + 1, p ^ 1);
        issueV(f0);
        CP_COMMIT();

        // ---- S = Qr Kr^T + Qi Ki^T (registers) ----
        float sacc[2][4][4] = {};
#pragma unroll
        for (int ks = 0; ks < 4; ks++) {
            uint32_t aR[2][4], aI[2][4];
#pragma unroll
            for (int mt = 0; mt < 2; mt++) {
                uint32_t rofs = (uint32_t)((wm * 32 + mt * 16) * 72 + ks * 16) * 2u + lofs2;
                ldsm4(sb + OQR + rofs, aR[mt]);
                ldsm4(sb + OQI + rofs, aI[mt]);
            }
            uint32_t bR[2][4], bI[2][4];
#pragma unroll
            for (int ntp = 0; ntp < 2; ntp++) {
                uint32_t rofs = (uint32_t)((wn * 32 + ntp * 16) * 72 + ks * 16) * 2u + lofs2;
                ldsm4(aK[p] + rofs, bR[ntp]);
                ldsm4(aK[p] + 9216u + rofs, bI[ntp]);
            }
#pragma unroll
            for (int mt = 0; mt < 2; mt++)
#pragma unroll
                for (int ntp = 0; ntp < 2; ntp++)
#pragma unroll
                    for (int sub = 0; sub < 2; sub++) {
                        int nt = ntp * 2 + sub;
                        uint32_t b2r[2] = { bR[ntp][sub], bR[ntp][sub + 2] };
                        uint32_t b2i[2] = { bI[ntp][sub], bI[ntp][sub + 2] };
                        mma16(sacc[mt][nt], aR[mt], b2r);
                        mma16(sacc[mt][nt], aI[mt], b2i);
                    }
        }

        // ---- mask tail cols ----
        if (f0 + 64 > FF) {
#pragma unroll
            for (int nt = 0; nt < 4; nt++) {
                int cb = f0 + wn * 32 + nt * 8 + 2 * tg;
#pragma unroll
                for (int mt = 0; mt < 2; mt++) {
                    if (cb >= FF)     { sacc[mt][nt][0] = -1e30f; sacc[mt][nt][2] = -1e30f; }
                    if (cb + 1 >= FF) { sacc[mt][nt][1] = -1e30f; sacc[mt][nt][3] = -1e30f; }
                }
            }
        }

        // ---- register softmax ----
        float rmax[2][2] = { {-1e30f, -1e30f}, {-1e30f, -1e30f} };
#pragma unroll
        for (int mt = 0; mt < 2; mt++)
#pragma unroll
            for (int nt = 0; nt < 4; nt++) {
                rmax[mt][0] = fmaxf(rmax[mt][0], fmaxf(sacc[mt][nt][0], sacc[mt][nt][1]));
                rmax[mt][1] = fmaxf(rmax[mt][1], fmaxf(sacc[mt][nt][2], sacc[mt][nt][3]));
            }
#pragma unroll
        for (int off = 1; off < 4; off <<= 1) {
#pragma unroll
            for (int mt = 0; mt < 2; mt++) {
                rmax[mt][0] = fmaxf(rmax[mt][0], __shfl_xor_sync(0xffffffffu, rmax[mt][0], off));
                rmax[mt][1] = fmaxf(rmax[mt][1], __shfl_xor_sync(0xffffffffu, rmax[mt][1], off));
            }
        }
        if (tg == 0) {
#pragma unroll
            for (int mt = 0; mt < 2; mt++) {
                sWmax[(wm * 32 + mt * 16 + g) * 2 + wn]     = rmax[mt][0];
                sWmax[(wm * 32 + mt * 16 + 8 + g) * 2 + wn] = rmax[mt][1];
            }
        }
        __syncthreads();

        float alpha[2][2], rsum[2][2] = {};
#pragma unroll
        for (int mt = 0; mt < 2; mt++)
#pragma unroll
            for (int hh = 0; hh < 2; hh++) {
                int row = wm * 32 + mt * 16 + hh * 8 + g;
                float mnew = fmaxf(m_run[mt][hh], fmaxf(sWmax[row * 2], sWmax[row * 2 + 1]));
                alpha[mt][hh] = __expf(m_run[mt][hh] - mnew);
                m_run[mt][hh] = mnew;
            }
#pragma unroll
        for (int mt = 0; mt < 2; mt++)
#pragma unroll
            for (int nt = 0; nt < 4; nt++) {
                float p0 = __expf(sacc[mt][nt][0] - m_run[mt][0]);
                float p1 = __expf(sacc[mt][nt][1] - m_run[mt][0]);
                float p2 = __expf(sacc[mt][nt][2] - m_run[mt][1]);
                float p3 = __expf(sacc[mt][nt][3] - m_run[mt][1]);
                rsum[mt][0] += p0 + p1;
                rsum[mt][1] += p2 + p3;
                int colo = wn * 32 + nt * 8 + 2 * tg;
                int r0 = wm * 32 + mt * 16 + g;
                *(__half2*)(sP + r0 * 72 + colo)       = __floats2half2_rn(p0, p1);
                *(__half2*)(sP + (r0 + 8) * 72 + colo) = __floats2half2_rn(p2, p3);
            }
#pragma unroll
        for (int off = 1; off < 4; off <<= 1) {
#pragma unroll
            for (int mt = 0; mt < 2; mt++) {
                rsum[mt][0] += __shfl_xor_sync(0xffffffffu, rsum[mt][0], off);
                rsum[mt][1] += __shfl_xor_sync(0xffffffffu, rsum[mt][1], off);
            }
        }
        if (tg == 0) {
#pragma unroll
            for (int mt = 0; mt < 2; mt++) {
                sWsum[(wm * 32 + mt * 16 + g) * 2 + wn]     = rsum[mt][0];
                sWsum[(wm * 32 + mt * 16 + 8 + g) * 2 + wn] = rsum[mt][1];
            }
        }
        // rescale accumulators
#pragma unroll
        for (int mt = 0; mt < 2; mt++)
#pragma unroll
            for (int nt = 0; nt < 4; nt++) {
                accR[mt][nt][0] *= alpha[mt][0]; accR[mt][nt][1] *= alpha[mt][0];
                accR[mt][nt][2] *= alpha[mt][1]; accR[mt][nt][3] *= alpha[mt][1];
                accI[mt][nt][0] *= alpha[mt][0]; accI[mt][nt][1] *= alpha[mt][0];
                accI[mt][nt][2] *= alpha[mt][1]; accI[mt][nt][3] *= alpha[mt][1];
            }
        CP_WAITALL();
        __syncthreads();

#pragma unroll
        for (int mt = 0; mt < 2; mt++)
#pragma unroll
            for (int hh = 0; hh < 2; hh++) {
                int row = wm * 32 + mt * 16 + hh * 8 + g;
                l_run[mt][hh] = l_run[mt][hh] * alpha[mt][hh] + sWsum[row * 2] + sWsum[row * 2 + 1];
            }

        // ---- O += P @ V ----
#pragma unroll
        for (int ks = 0; ks < 4; ks++) {
            uint32_t aP[2][4];
#pragma unroll
            for (int mt = 0; mt < 2; mt++) {
                uint32_t rofs = (uint32_t)((wm * 32 + mt * 16) * 72 + ks * 16) * 2u + lofs2;
                ldsm4(sb + OP + rofs, aP[mt]);
            }
            uint32_t bVr[2][4], bVi[2][4];
#pragma unroll
            for (int ntp = 0; ntp < 2; ntp++) {
                uint32_t rofs = (uint32_t)((wn * 32 + ntp * 16) * 72 + ks * 16) * 2u + lofs2;
                ldsm4(aV + rofs, bVr[ntp]);
                ldsm4(aV + 9216u + rofs, bVi[ntp]);
            }
#pragma unroll
            for (int mt = 0; mt < 2; mt++)
#pragma unroll
                for (int ntp = 0; ntp < 2; ntp++)
#pragma unroll
                    for (int sub = 0; sub < 2; sub++) {
                        int nt = ntp * 2 + sub;
                        uint32_t b2r[2] = { bVr[ntp][sub], bVr[ntp][sub + 2] };
                        uint32_t b2i[2] = { bVi[ntp][sub], bVi[ntp][sub + 2] };
                        mma16(accR[mt][nt], aP[mt], b2r);
                        mma16(accI[mt][nt], aP[mt], b2i);
                    }
        }
    }
    __syncthreads();

    // ---- epilogue: divide by l, write f32 ----
#pragma unroll
    for (int mt = 0; mt < 2; mt++) {
        int row = wm * 32 + mt * 16 + g;
        float li0 = 1.0f / l_run[mt][0];
        float li1 = 1.0f / l_run[mt][1];
        int q = q0 + row;
#pragma unroll
        for (int nt = 0; nt < 4; nt++) {
            int col = wn * 32 + nt * 8 + 2 * tg;
            if (q < FF) {
                size_t gg = baseF + (size_t)q * EE + col;
                *(float2*)&Outr[gg] = make_float2(accR[mt][nt][0] * li0, accR[mt][nt][1] * li0);
                *(float2*)&Outi[gg] = make_float2(accI[mt][nt][0] * li0, accI[mt][nt][1] * li0);
            }
            if (q + 8 < FF) {
                size_t gg = baseF + (size_t)(q + 8) * EE + col;
                *(float2*)&Outr[gg] = make_float2(accR[mt][nt][2] * li1, accR[mt][nt][3] * li1);
                *(float2*)&Outi[gg] = make_float2(accI[mt][nt][2] * li1, accI[mt][nt][3] * li1);
            }
        }
    }
}

// ---------------- host launcher ----------------
extern "C" void kernel_launch(void* const* d_in, const int* in_sizes, int n_in,
                              void* d_out, int out_size)
{
    const float* x    = (const float*)d_in[0];
    const float* gam  = (const float*)d_in[1];
    const float* bet  = (const float*)d_in[2];
    const float* Wq_r = (const float*)d_in[3];
    const float* bq_r = (const float*)d_in[4];
    const float* Wq_i = (const float*)d_in[5];
    const float* bq_i = (const float*)d_in[6];
    const float* Wk_r = (const float*)d_in[7];
    const float* bk_r = (const float*)d_in[8];
    const float* Wk_i = (const float*)d_in[9];
    const float* bk_i = (const float*)d_in[10];
    const float* Wv_r = (const float*)d_in[11];
    const float* bv_r = (const float*)d_in[12];
    const float* Wv_i = (const float*)d_in[13];
    const float* bv_i = (const float*)d_in[14];
    const float* Wo   = (const float*)d_in[15];
    float* out = (float*)d_out;

    static int attr_set = 0;
    if (!attr_set) {
        cudaFuncSetAttribute(attn_tc, cudaFuncAttributeMaxDynamicSharedMemorySize, ATTN_SMEM);
        attr_set = 1;
    }

    float *p_xr, *p_xi, *p_Or, *p_Oi, *p_y;
    __half *p_Qhr, *p_Qhi, *p_Khr, *p_Khi, *p_VtHr, *p_VtHi;
    cudaGetSymbolAddress((void**)&p_xr, g_xr);
    cudaGetSymbolAddress((void**)&p_xi, g_xi);
    cudaGetSymbolAddress((void**)&p_Qhr, g_Qhr);
    cudaGetSymbolAddress((void**)&p_Qhi, g_Qhi);
    cudaGetSymbolAddress((void**)&p_Khr, g_Khr);
    cudaGetSymbolAddress((void**)&p_Khi, g_Khi);
    cudaGetSymbolAddress((void**)&p_VtHr, g_VtHr);
    cudaGetSymbolAddress((void**)&p_VtHi, g_VtHi);
    cudaGetSymbolAddress((void**)&p_Or, g_Or);
    cudaGetSymbolAddress((void**)&p_Oi, g_Oi);
    cudaGetSymbolAddress((void**)&p_y,  g_y);

    const int MF = BB * FF;      // 8196
    const int ML = BB * LL;      // 16384

    twiddle_init<<<9, 256>>>();
    ln_kernel<<<BB * LL, 256>>>(x, gam, bet);
    {
        dim3 g(EE / 32, LL / 32, BB), blk(32, 8);
        transpose_LE_to_EL<<<g, blk>>>();
    }
    rfft_kernel<<<BB * EE, 256>>>();
    {
        GemmBatch gb;
        gb.g[0] = { p_xr, Wq_r, bq_r, p_Qhr, 1, 0.125f };
        gb.g[1] = { p_xi, Wq_i, bq_i, p_Qhi, 1, 0.125f };
        gb.g[2] = { p_xr, Wk_r, bk_r, p_Khr, 1, 1.0f };
        gb.g[3] = { p_xi, Wk_i, bk_i, p_Khi, 1, 1.0f };
        gb.g[4] = { p_xr, Wv_r, bv_r, p_VtHr, 2, 1.0f };
        gb.g[5] = { p_xi, Wv_i, bv_i, p_VtHi, 2, 1.0f };
        dim3 g((MF + 127) / 128, 8, 6);
        gemm_tc<<<g, 256>>>(gb, MF);
    }
    {
        dim3 g((FF + 127) / 128, BB * HH);
        attn_tc<<<g, 256, ATTN_SMEM>>>(p_Qhr, p_Qhi, p_Khr, p_Khi, p_Or, p_Oi);
    }
    irfft_kernel<<<BB * EE, 256>>>();
    {
        dim3 g(LL / 32, EE / 32, BB), blk(32, 8);
        transpose_EL_to_LE<<<g, blk>>>();
    }
    {
        GemmBatch gb;
        gb.g[0] = { p_y, Wo, nullptr, out, 0, 1.0f };
        gb.g[1] = gb.g[0]; gb.g[2] = gb.g[0]; gb.g[3] = gb.g[0];
        gb.g[4] = gb.g[0]; gb.g[5] = gb.g[0];
        dim3 g((ML + 127) / 128, 8, 1);
        gemm_tc<<<g, 256>>>(gb, ML);
    }
}

// round 15
// speedup vs baseline: 2.7361x; 1.2098x over previous
#include <cuda_runtime.h>
#include <cuda_fp16.h>
#include <math.h>
#include <stdint.h>

// ---------------- problem constants ----------------
#define BB 4
#define LL 4096
#define EE 512
#define FF 2049
#define FFP 2064           // padded F for transposed V
#define HH 8
#define DD 64
#define FFTM 2048

// ---------------- scratch (device globals; allocation-free) ----------------
__device__ float2 g_stats[BB * LL];            // (mean, rstd) per row
__device__ float g_xt[BB * EE * LL];
__device__ float g_xr[BB * FF * EE];
__device__ float g_xi[BB * FF * EE];
__device__ __half g_Qhr[BB * FF * EE];
__device__ __half g_Qhi[BB * FF * EE];
__device__ __half g_Khr[BB * FF * EE];
__device__ __half g_Khi[BB * FF * EE];
__device__ __half g_VtHr[BB * HH * DD * FFP];   // V transposed [bh][d][FFP]
__device__ __half g_VtHi[BB * HH * DD * FFP];
__device__ float g_Or[BB * FF * EE];
__device__ float g_Oi[BB * FF * EE];
__device__ float g_y [BB * LL * EE];
__device__ float2 g_twS[1024];
__device__ float2 g_twP[FF];

// ---------------- helpers ----------------
__device__ __forceinline__ void mma16(float* c, const uint32_t* a, const uint32_t* b) {
    asm volatile(
        "mma.sync.aligned.m16n8k16.row.col.f32.f16.f16.f32 "
        "{%0,%1,%2,%3},{%4,%5,%6,%7},{%8,%9},{%0,%1,%2,%3};"
        : "+f"(c[0]), "+f"(c[1]), "+f"(c[2]), "+f"(c[3])
        : "r"(a[0]), "r"(a[1]), "r"(a[2]), "r"(a[3]),
          "r"(b[0]), "r"(b[1]));
}
__device__ __forceinline__ void ldsm4(uint32_t addr, uint32_t* r) {
    asm volatile("ldmatrix.sync.aligned.m8n8.x4.shared.b16 {%0,%1,%2,%3}, [%4];"
                 : "=r"(r[0]), "=r"(r[1]), "=r"(r[2]), "=r"(r[3]) : "r"(addr));
}
__device__ __forceinline__ uint32_t smem_u32(const void* p) {
    uint32_t a;
    asm("{ .reg .u64 t; cvta.to.shared.u64 t, %1; cvt.u32.u64 %0, t; }" : "=r"(a) : "l"(p));
    return a;
}
__device__ __forceinline__ void cpa16(uint32_t dst, const void* src, uint32_t bytes) {
    asm volatile("cp.async.cg.shared.global [%0], [%1], 16, %2;"
                 :: "r"(dst), "l"(src), "r"(bytes) : "memory");
}
#define CP_COMMIT()  asm volatile("cp.async.commit_group;" ::: "memory")
#define CP_WAITALL() asm volatile("cp.async.wait_all;" ::: "memory")

// ---------------- twiddle table init ----------------
__global__ void twiddle_init()
{
    int t = blockIdx.x * 256 + threadIdx.x;
    if (t < 1024) {
        float sn, cs; sincospif(-(float)t * (1.0f / 1024.0f), &sn, &cs);
        g_twS[t] = make_float2(cs, sn);
    }
    if (t < FF) {
        float sn, cs; sincospif(-(float)t * (1.0f / 2048.0f), &sn, &cs);
        g_twP[t] = make_float2(cs, sn);
    }
}

// ---------------- LayerNorm stats (warp per row) ----------------
__global__ void ln_stats(const float* __restrict__ x)
{
    int row = blockIdx.x * 8 + (threadIdx.x >> 5);
    int lane = threadIdx.x & 31;
    const float4* xr = (const float4*)(x + (size_t)row * EE);
    float s = 0.f, s2 = 0.f;
#pragma unroll
    for (int i = 0; i < 4; i++) {
        float4 v = xr[lane + i * 32];
        s  += v.x + v.y + v.z + v.w;
        s2 += v.x * v.x + v.y * v.y + v.z * v.z + v.w * v.w;
    }
#pragma unroll
    for (int off = 16; off; off >>= 1) {
        s  += __shfl_xor_sync(0xffffffffu, s,  off);
        s2 += __shfl_xor_sync(0xffffffffu, s2, off);
    }
    if (lane == 0) {
        float mean = s * (1.0f / EE);
        float var  = s2 * (1.0f / EE) - mean * mean;
        g_stats[row] = make_float2(mean, rsqrtf(var + 1e-5f));
    }
}

// ---------------- fused LN + transpose [B][L][E] -> [B][E][L] ----------------
__global__ void transpose_LE_to_EL_ln(const float* __restrict__ x,
                                      const float* __restrict__ gam,
                                      const float* __restrict__ bet)
{
    __shared__ float tile[32][33];
    int b  = blockIdx.z;
    int e0 = blockIdx.x * 32;
    int l0 = blockIdx.y * 32;
    const float* s = x + ((size_t)b * LL + l0) * EE + e0;
    float gv = gam[e0 + threadIdx.x];
    float bv = bet[e0 + threadIdx.x];
    for (int rr = threadIdx.y; rr < 32; rr += 8) {
        float2 st = g_stats[b * LL + l0 + rr];
        tile[rr][threadIdx.x] = (s[(size_t)rr * EE + threadIdx.x] - st.x) * st.y * gv + bv;
    }
    __syncthreads();
    float* d = g_xt + ((size_t)b * EE + e0) * LL + l0;
    for (int rr = threadIdx.y; rr < 32; rr += 8)
        d[(size_t)rr * LL + threadIdx.x] = tile[threadIdx.x][rr];
}

__global__ void transpose_EL_to_LE()
{
    __shared__ float tile[32][33];
    int b  = blockIdx.z;
    int l0 = blockIdx.x * 32;
    int e0 = blockIdx.y * 32;
    const float* s = g_xt + ((size_t)b * EE + e0) * LL + l0;
    for (int rr = threadIdx.y; rr < 32; rr += 8)
        tile[rr][threadIdx.x] = s[(size_t)rr * LL + threadIdx.x];
    __syncthreads();
    float* d = g_y + ((size_t)b * LL + l0) * EE + e0;
    for (int rr = threadIdx.y; rr < 32; rr += 8)
        d[(size_t)rr * EE + threadIdx.x] = tile[threadIdx.x][rr];
}

// ---------------- Stockham FFT (complex, length 2048, 256 threads) ----------------
__device__ __forceinline__ float2* fft_stockham2048(float2* src, float2* dst,
                                                    const float2* __restrict__ tw, int t)
{
#pragma unroll 1
    for (int stage = 0; stage < 11; stage++) {
        int s = 1 << stage;
#pragma unroll
        for (int i = 0; i < 4; i++) {
            int j = t + (i << 8);
            int p = j >> stage;
            int q = j & (s - 1);
            float2 u = src[q + (p << stage)];
            float2 v = src[q + ((p + (1024 >> stage)) << stage)];
            float2 ss = make_float2(u.x + v.x, u.y + v.y);
            float2 dd = make_float2(u.x - v.x, u.y - v.y);
            float2 w  = tw[p << stage];
            int od = q + (p << (stage + 1));
            dst[od]     = ss;
            dst[od + s] = make_float2(dd.x * w.x - dd.y * w.y,
                                      dd.x * w.y + dd.y * w.x);
        }
        __syncthreads();
        float2* tmp = src; src = dst; dst = tmp;
    }
    return src;
}

__global__ void rfft_kernel()
{
    __shared__ float2 bufA[FFTM], bufB[FFTM];
    __shared__ float2 tw[1024];
    int t  = threadIdx.x;
    int be = blockIdx.x;
    int b  = be >> 9, e = be & 511;

    const float2* src = (const float2*)(g_xt + (size_t)be * LL);
#pragma unroll
    for (int i = 0; i < 8; i++) bufA[t + (i << 8)] = src[t + (i << 8)];
#pragma unroll
    for (int i = 0; i < 4; i++) tw[t + (i << 8)] = g_twS[t + (i << 8)];
    __syncthreads();
    float2* Z = fft_stockham2048(bufA, bufB, tw, t);

    const float scale = 1.0f / 64.0f;
    for (int k = t; k <= FFTM; k += 256) {
        float2 zk = Z[k & (FFTM - 1)];
        float2 zm = Z[(FFTM - k) & (FFTM - 1)];
        float Er  = 0.5f * (zk.x + zm.x);
        float Eii = 0.5f * (zk.y - zm.y);
        float Or0 = 0.5f * (zk.x - zm.x);
        float Oi0 = 0.5f * (zk.y + zm.y);
        float2 w = g_twP[k];
        float ux = w.x * Or0 - w.y * Oi0;
        float uy = w.x * Oi0 + w.y * Or0;
        size_t g = ((size_t)b * FF + k) * EE + e;
        g_xr[g] = (Er  + uy) * scale;
        g_xi[g] = (Eii - ux) * scale;
    }
}

__global__ void irfft_kernel()
{
    __shared__ float2 bufA[FFTM], bufB[FFTM];
    __shared__ float2 tw[1024];
    int t  = threadIdx.x;
    int be = blockIdx.x;
    int b  = be >> 9, e = be & 511;

#pragma unroll
    for (int i = 0; i < 4; i++) {
        float2 w = g_twS[t + (i << 8)];
        tw[t + (i << 8)] = make_float2(w.x, -w.y);
    }
    for (int k = t; k < FFTM; k += 256) {
        size_t gk = ((size_t)b * FF + k) * EE + e;
        size_t gm = ((size_t)b * FF + (FFTM - k)) * EE + e;
        float Xr_k = g_Or[gk];
        float Xi_k = (k == 0) ? 0.0f : g_Oi[gk];
        float Xr_m = g_Or[gm];
        float Xi_m = (k == 0) ? 0.0f : g_Oi[gm];
        float Er  = 0.5f * (Xr_k + Xr_m);
        float Ei  = 0.5f * (Xi_k - Xi_m);
        float Or0 = 0.5f * (Xr_k - Xr_m);
        float Oi0 = 0.5f * (Xi_k + Xi_m);
        float2 w = g_twP[k];
        float cs = w.x, sn = -w.y;
        float ux = cs * Or0 - sn * Oi0;
        float uy = cs * Oi0 + sn * Or0;
        bufA[k] = make_float2(Er - uy, Ei + ux);
    }
    __syncthreads();
    float2* w = fft_stockham2048(bufA, bufB, tw, t);

    float2* out = (float2*)(g_xt + (size_t)be * LL);
    const float sc = 1.0f / 32.0f;
#pragma unroll
    for (int i = 0; i < 8; i++) {
        int n = t + (i << 8);
        float2 z = w[n];
        out[n] = make_float2(z.x * sc, z.y * sc);
    }
}

// ---------------- fp16 GEMM (ldmatrix + m16n8k16), batched; epilogue modes ----------------
// mode 0: f32 out.  mode 1: half2 out (scaled).  mode 2: half transposed-V out.
// block tile 128m x 64n, k-stage 64.  8 warps: 4x2 of 32x32 warp tiles.
struct GemmPtrs { const float *A, *W, *bias; void *C; int mode; float scale; };
struct GemmBatch { GemmPtrs g[6]; };

#define GLD 72
__global__ void __launch_bounds__(256) gemm_tc(GemmBatch batch, int M)
{
    __shared__ __half sA[128 * GLD];   // 18432 B
    __shared__ __half sB[64 * GLD];    //  9216 B
    GemmPtrs gp = batch.g[blockIdx.z];
    int m0 = blockIdx.x * 128, n0 = blockIdx.y * 64;
    int t = threadIdx.x, lane = t & 31, w = t >> 5;
    int g = lane >> 2, t4 = lane & 3;
    int wm = w >> 1, wn = w & 1;
    uint32_t sbA = smem_u32(sA), sbB = smem_u32(sB);

    int lrow = (lane & 7) + ((lane >> 3) & 1) * 8;
    int lcol = (lane >> 4) * 8;
    uint32_t lofs2 = (uint32_t)(lrow * GLD + lcol) * 2u;

    float acc[2][4][4] = {};

    for (int k0 = 0; k0 < 512; k0 += 64) {
        // A: 128 rows x 64 cols -> half
#pragma unroll
        for (int i = 0; i < 8; i++) {
            int id = t + i * 256;
            int r = id >> 4, c4 = (id & 15) * 4;
            float4 v = make_float4(0.f, 0.f, 0.f, 0.f);
            if (m0 + r < M) v = *(const float4*)&gp.A[(size_t)(m0 + r) * 512 + k0 + c4];
            __half2 h01 = __floats2half2_rn(v.x, v.y);
            __half2 h23 = __floats2half2_rn(v.z, v.w);
            *(__half2*)(sA + r * GLD + c4)     = h01;
            *(__half2*)(sA + r * GLD + c4 + 2) = h23;
        }
        // B: 64 rows x 64 cols -> half
#pragma unroll
        for (int i = 0; i < 4; i++) {
            int id = t + i * 256;
            int r = id >> 4, c4 = (id & 15) * 4;
            float4 v = *(const float4*)&gp.W[(size_t)(n0 + r) * 512 + k0 + c4];
            __half2 h01 = __floats2half2_rn(v.x, v.y);
            __half2 h23 = __floats2half2_rn(v.z, v.w);
            *(__half2*)(sB + r * GLD + c4)     = h01;
            *(__half2*)(sB + r * GLD + c4 + 2) = h23;
        }
        __syncthreads();
#pragma unroll
        for (int ks = 0; ks < 4; ks++) {
            uint32_t aF[2][4];
#pragma unroll
            for (int mt = 0; mt < 2; mt++)
                ldsm4(sbA + (uint32_t)((wm * 32 + mt * 16) * GLD + ks * 16) * 2u + lofs2, aF[mt]);
            uint32_t bF[2][4];
#pragma unroll
            for (int ntp = 0; ntp < 2; ntp++)
                ldsm4(sbB + (uint32_t)((wn * 32 + ntp * 16) * GLD + ks * 16) * 2u + lofs2, bF[ntp]);
#pragma unroll
            for (int mt = 0; mt < 2; mt++)
#pragma unroll
                for (int ntp = 0; ntp < 2; ntp++)
#pragma unroll
                    for (int sub = 0; sub < 2; sub++) {
                        uint32_t b2[2] = { bF[ntp][sub], bF[ntp][sub + 2] };
                        mma16(acc[mt][ntp * 2 + sub], aF[mt], b2);
                    }
        }
        __syncthreads();
    }
#pragma unroll
    for (int nt = 0; nt < 4; nt++) {
        int col = n0 + wn * 32 + nt * 8 + 2 * t4;
        float b0 = gp.bias ? gp.bias[col] : 0.f;
        float b1 = gp.bias ? gp.bias[col + 1] : 0.f;
#pragma unroll
        for (int mt = 0; mt < 2; mt++) {
#pragma unroll
            for (int half = 0; half < 2; half++) {
                int row = m0 + wm * 32 + mt * 16 + half * 8 + g;
                if (row >= M) continue;
                float v0 = acc[mt][nt][half * 2 + 0] + b0;
                float v1 = acc[mt][nt][half * 2 + 1] + b1;
                if (gp.mode == 0) {
                    *(float2*)((float*)gp.C + (size_t)row * 512 + col) = make_float2(v0, v1);
                } else if (gp.mode == 1) {
                    __half2 hv = __floats2half2_rn(v0 * gp.scale, v1 * gp.scale);
                    *(__half2*)((__half*)gp.C + (size_t)row * 512 + col) = hv;
                } else {
                    int bb = row / FF, f = row - bb * FF;
                    int hh = col >> 6, dd = col & 63;
                    __half* vh = (__half*)gp.C;
                    size_t gbase = ((size_t)((bb * 8 + hh) * 64 + dd)) * FFP + f;
                    vh[gbase]       = __float2half_rn(v0);
                    vh[gbase + FFP] = __float2half_rn(v1);
                }
            }
        }
    }
}

// ---------------- fp16 flash attention (unchanged from round 14) ----------------
#define OQR 0
#define OQI 18432
#define OK0 36864
#define OK1 55296
#define OV  73728
#define OP  92160
#define OST 110592
#define ATTN_SMEM 112640
__global__ void __launch_bounds__(256) attn_tc(
    const __half* __restrict__ Qhr, const __half* __restrict__ Qhi,
    const __half* __restrict__ Khr, const __half* __restrict__ Khi,
    float* __restrict__ Outr, float* __restrict__ Outi)
{
    extern __shared__ char smc[];
    __half* sP  = (__half*)(smc + OP);
    float* sWmax = (float*)(smc + OST);
    float* sWsum = sWmax + 256;

    int bh = blockIdx.y;
    int b = bh >> 3, h = bh & 7;
    int q0 = blockIdx.x * 128;
    int t = threadIdx.x, lane = t & 31, w = t >> 5;
    int g = lane >> 2, tg = lane & 3;
    int wm = w >> 1, wn = w & 1;
    const size_t baseF = (size_t)b * FF * EE + h * DD;
    const size_t baseH = (size_t)(b * FF) * 512 + h * 64;

    uint32_t sb = smem_u32(smc);
    uint32_t aK[2] = { sb + OK0, sb + OK1 };
    uint32_t aV = sb + OV;

    int lrow = (lane & 7) + ((lane >> 3) & 1) * 8;
    int lcol = (lane >> 4) * 8;
    uint32_t lofs2 = (uint32_t)(lrow * 72 + lcol) * 2u;

    auto issueK = [&](int kt, int p) {
#pragma unroll
        for (int j = 0; j < 4; j++) {
            int idx = t + j * 256;
            int comp = idx >> 9;
            int rem = idx & 511;
            int f = rem >> 3, c = rem & 7;
            int gf = kt * 64 + f;
            const __half* srcb = comp ? Khi : Khr;
            const __half* src = srcb;
            uint32_t bytes = 0;
            if (gf < FF) { src = srcb + baseH + (size_t)gf * 512 + c * 8; bytes = 16; }
            cpa16(aK[p] + (uint32_t)(comp * 4608 + f * 72 + c * 8) * 2u, src, bytes);
        }
    };
    auto issueV = [&](int f0) {
#pragma unroll
        for (int j = 0; j < 4; j++) {
            int idx = t + j * 256;
            int comp = idx >> 9;
            int rem = idx & 511;
            int d = rem >> 3, c = rem & 7;
            int fb = f0 + c * 8;
            const __half* srcb = comp ? g_VtHi : g_VtHr;
            const __half* src = srcb;
            uint32_t bytes = 0;
            if (fb < FF) {
                src = srcb + (size_t)(bh * 64 + d) * FFP + fb;
                bytes = (fb + 8 <= FF) ? 16u : (uint32_t)(FF - fb) * 2u;
            }
            cpa16(aV + (uint32_t)(comp * 4608 + d * 72 + c * 8) * 2u, src, bytes);
        }
    };

    issueK(0, 0);
    CP_COMMIT();

    __half* sQr = (__half*)smc;
    __half* sQi = (__half*)(smc + OQI);
    for (int idx = t; idx < 4096; idx += 256) {
        int q = idx >> 5, c = idx & 31;
        int gq = q0 + q;
        __half2 vr = __floats2half2_rn(0.f, 0.f), vi = vr;
        if (gq < FF) {
            vr = *(const __half2*)(Qhr + baseH + (size_t)gq * 512 + 2 * c);
            vi = *(const __half2*)(Qhi + baseH + (size_t)gq * 512 + 2 * c);
        }
        *(__half2*)(sQr + q * 72 + 2 * c) = vr;
        *(__half2*)(sQi + q * 72 + 2 * c) = vi;
    }
    CP_WAITALL();

    float accR[2][4][4] = {}, accI[2][4][4] = {};
    float m_run[2][2] = { {-1e30f, -1e30f}, {-1e30f, -1e30f} };
    float l_run[2][2] = {};

    for (int it = 0; it < 33; it++) {
        int p = it & 1;
        int f0 = it * 64;
        __syncthreads();
        if (it < 32) issueK(it + 1, p ^ 1);
        issueV(f0);
        CP_COMMIT();

        float sacc[2][4][4] = {};
#pragma unroll
        for (int ks = 0; ks < 4; ks++) {
            uint32_t aR[2][4], aI[2][4];
#pragma unroll
            for (int mt = 0; mt < 2; mt++) {
                uint32_t rofs = (uint32_t)((wm * 32 + mt * 16) * 72 + ks * 16) * 2u + lofs2;
                ldsm4(sb + OQR + rofs, aR[mt]);
                ldsm4(sb + OQI + rofs, aI[mt]);
            }
            uint32_t bR[2][4], bI[2][4];
#pragma unroll
            for (int ntp = 0; ntp < 2; ntp++) {
                uint32_t rofs = (uint32_t)((wn * 32 + ntp * 16) * 72 + ks * 16) * 2u + lofs2;
                ldsm4(aK[p] + rofs, bR[ntp]);
                ldsm4(aK[p] + 9216u + rofs, bI[ntp]);
            }
#pragma unroll
            for (int mt = 0; mt < 2; mt++)
#pragma unroll
                for (int ntp = 0; ntp < 2; ntp++)
#pragma unroll
                    for (int sub = 0; sub < 2; sub++) {
                        int nt = ntp * 2 + sub;
                        uint32_t b2r[2] = { bR[ntp][sub], bR[ntp][sub + 2] };
                        uint32_t b2i[2] = { bI[ntp][sub], bI[ntp][sub + 2] };
                        mma16(sacc[mt][nt], aR[mt], b2r);
                        mma16(sacc[mt][nt], aI[mt], b2i);
                    }
        }

        if (f0 + 64 > FF) {
#pragma unroll
            for (int nt = 0; nt < 4; nt++) {
                int cb = f0 + wn * 32 + nt * 8 + 2 * tg;
#pragma unroll
                for (int mt = 0; mt < 2; mt++) {
                    if (cb >= FF)     { sacc[mt][nt][0] = -1e30f; sacc[mt][nt][2] = -1e30f; }
                    if (cb + 1 >= FF) { sacc[mt][nt][1] = -1e30f; sacc[mt][nt][3] = -1e30f; }
                }
            }
        }

        float rmax[2][2] = { {-1e30f, -1e30f}, {-1e30f, -1e30f} };
#pragma unroll
        for (int mt = 0; mt < 2; mt++)
#pragma unroll
            for (int nt = 0; nt < 4; nt++) {
                rmax[mt][0] = fmaxf(rmax[mt][0], fmaxf(sacc[mt][nt][0], sacc[mt][nt][1]));
                rmax[mt][1] = fmaxf(rmax[mt][1], fmaxf(sacc[mt][nt][2], sacc[mt][nt][3]));
            }
#pragma unroll
        for (int off = 1; off < 4; off <<= 1) {
#pragma unroll
            for (int mt = 0; mt < 2; mt++) {
                rmax[mt][0] = fmaxf(rmax[mt][0], __shfl_xor_sync(0xffffffffu, rmax[mt][0], off));
                rmax[mt][1] = fmaxf(rmax[mt][1], __shfl_xor_sync(0xffffffffu, rmax[mt][1], off));
            }
        }
        if (tg == 0) {
#pragma unroll
            for (int mt = 0; mt < 2; mt++) {
                sWmax[(wm * 32 + mt * 16 + g) * 2 + wn]     = rmax[mt][0];
                sWmax[(wm * 32 + mt * 16 + 8 + g) * 2 + wn] = rmax[mt][1];
            }
        }
        __syncthreads();

        float alpha[2][2], rsum[2][2] = {};
#pragma unroll
        for (int mt = 0; mt < 2; mt++)
#pragma unroll
            for (int hh = 0; hh < 2; hh++) {
                int row = wm * 32 + mt * 16 + hh * 8 + g;
                float mnew = fmaxf(m_run[mt][hh], fmaxf(sWmax[row * 2], sWmax[row * 2 + 1]));
                alpha[mt][hh] = __expf(m_run[mt][hh] - mnew);
                m_run[mt][hh] = mnew;
            }
#pragma unroll
        for (int mt = 0; mt < 2; mt++)
#pragma unroll
            for (int nt = 0; nt < 4; nt++) {
                float p0 = __expf(sacc[mt][nt][0] - m_run[mt][0]);
                float p1 = __expf(sacc[mt][nt][1] - m_run[mt][0]);
                float p2 = __expf(sacc[mt][nt][2] - m_run[mt][1]);
                float p3 = __expf(sacc[mt][nt][3] - m_run[mt][1]);
                rsum[mt][0] += p0 + p1;
                rsum[mt][1] += p2 + p3;
                int colo = wn * 32 + nt * 8 + 2 * tg;
                int r0 = wm * 32 + mt * 16 + g;
                *(__half2*)(sP + r0 * 72 + colo)       = __floats2half2_rn(p0, p1);
                *(__half2*)(sP + (r0 + 8) * 72 + colo) = __floats2half2_rn(p2, p3);
            }
#pragma unroll
        for (int off = 1; off < 4; off <<= 1) {
#pragma unroll
            for (int mt = 0; mt < 2; mt++) {
                rsum[mt][0] += __shfl_xor_sync(0xffffffffu, rsum[mt][0], off);
                rsum[mt][1] += __shfl_xor_sync(0xffffffffu, rsum[mt][1], off);
            }
        }
        if (tg == 0) {
#pragma unroll
            for (int mt = 0; mt < 2; mt++) {
                sWsum[(wm * 32 + mt * 16 + g) * 2 + wn]     = rsum[mt][0];
                sWsum[(wm * 32 + mt * 16 + 8 + g) * 2 + wn] = rsum[mt][1];
            }
        }
#pragma unroll
        for (int mt = 0; mt < 2; mt++)
#pragma unroll
            for (int nt = 0; nt < 4; nt++) {
                accR[mt][nt][0] *= alpha[mt][0]; accR[mt][nt][1] *= alpha[mt][0];
                accR[mt][nt][2] *= alpha[mt][1]; accR[mt][nt][3] *= alpha[mt][1];
                accI[mt][nt][0] *= alpha[mt][0]; accI[mt][nt][1] *= alpha[mt][0];
                accI[mt][nt][2] *= alpha[mt][1]; accI[mt][nt][3] *= alpha[mt][1];
            }
        CP_WAITALL();
        __syncthreads();

#pragma unroll
        for (int mt = 0; mt < 2; mt++)
#pragma unroll
            for (int hh = 0; hh < 2; hh++) {
                int row = wm * 32 + mt * 16 + hh * 8 + g;
                l_run[mt][hh] = l_run[mt][hh] * alpha[mt][hh] + sWsum[row * 2] + sWsum[row * 2 + 1];
            }

#pragma unroll
        for (int ks = 0; ks < 4; ks++) {
            uint32_t aP[2][4];
#pragma unroll
            for (int mt = 0; mt < 2; mt++) {
                uint32_t rofs = (uint32_t)((wm * 32 + mt * 16) * 72 + ks * 16) * 2u + lofs2;
                ldsm4(sb + OP + rofs, aP[mt]);
            }
            uint32_t bVr[2][4], bVi[2][4];
#pragma unroll
            for (int ntp = 0; ntp < 2; ntp++) {
                uint32_t rofs = (uint32_t)((wn * 32 + ntp * 16) * 72 + ks * 16) * 2u + lofs2;
                ldsm4(aV + rofs, bVr[ntp]);
                ldsm4(aV + 9216u + rofs, bVi[ntp]);
            }
#pragma unroll
            for (int mt = 0; mt < 2; mt++)
#pragma unroll
                for (int ntp = 0; ntp < 2; ntp++)
#pragma unroll
                    for (int sub = 0; sub < 2; sub++) {
                        int nt = ntp * 2 + sub;
                        uint32_t b2r[2] = { bVr[ntp][sub], bVr[ntp][sub + 2] };
                        uint32_t b2i[2] = { bVi[ntp][sub], bVi[ntp][sub + 2] };
                        mma16(accR[mt][nt], aP[mt], b2r);
                        mma16(accI[mt][nt], aP[mt], b2i);
                    }
        }
    }
    __syncthreads();

#pragma unroll
    for (int mt = 0; mt < 2; mt++) {
        int row = wm * 32 + mt * 16 + g;
        float li0 = 1.0f / l_run[mt][0];
        float li1 = 1.0f / l_run[mt][1];
        int q = q0 + row;
#pragma unroll
        for (int nt = 0; nt < 4; nt++) {
            int col = wn * 32 + nt * 8 + 2 * tg;
            if (q < FF) {
                size_t gg = baseF + (size_t)q * EE + col;
                *(float2*)&Outr[gg] = make_float2(accR[mt][nt][0] * li0, accR[mt][nt][1] * li0);
                *(float2*)&Outi[gg] = make_float2(accI[mt][nt][0] * li0, accI[mt][nt][1] * li0);
            }
            if (q + 8 < FF) {
                size_t gg = baseF + (size_t)(q + 8) * EE + col;
                *(float2*)&Outr[gg] = make_float2(accR[mt][nt][2] * li1, accR[mt][nt][3] * li1);
                *(float2*)&Outi[gg] = make_float2(accI[mt][nt][2] * li1, accI[mt][nt][3] * li1);
            }
        }
    }
}

// ---------------- host launcher ----------------
extern "C" void kernel_launch(void* const* d_in, const int* in_sizes, int n_in,
                              void* d_out, int out_size)
{
    const float* x    = (const float*)d_in[0];
    const float* gam  = (const float*)d_in[1];
    const float* bet  = (const float*)d_in[2];
    const float* Wq_r = (const float*)d_in[3];
    const float* bq_r = (const float*)d_in[4];
    const float* Wq_i = (const float*)d_in[5];
    const float* bq_i = (const float*)d_in[6];
    const float* Wk_r = (const float*)d_in[7];
    const float* bk_r = (const float*)d_in[8];
    const float* Wk_i = (const float*)d_in[9];
    const float* bk_i = (const float*)d_in[10];
    const float* Wv_r = (const float*)d_in[11];
    const float* bv_r = (const float*)d_in[12];
    const float* Wv_i = (const float*)d_in[13];
    const float* bv_i = (const float*)d_in[14];
    const float* Wo   = (const float*)d_in[15];
    float* out = (float*)d_out;

    static int attr_set = 0;
    if (!attr_set) {
        cudaFuncSetAttribute(attn_tc, cudaFuncAttributeMaxDynamicSharedMemorySize, ATTN_SMEM);
        attr_set = 1;
    }

    float *p_xr, *p_xi, *p_Or, *p_Oi, *p_y;
    __half *p_Qhr, *p_Qhi, *p_Khr, *p_Khi, *p_VtHr, *p_VtHi;
    cudaGetSymbolAddress((void**)&p_xr, g_xr);
    cudaGetSymbolAddress((void**)&p_xi, g_xi);
    cudaGetSymbolAddress((void**)&p_Qhr, g_Qhr);
    cudaGetSymbolAddress((void**)&p_Qhi, g_Qhi);
    cudaGetSymbolAddress((void**)&p_Khr, g_Khr);
    cudaGetSymbolAddress((void**)&p_Khi, g_Khi);
    cudaGetSymbolAddress((void**)&p_VtHr, g_VtHr);
    cudaGetSymbolAddress((void**)&p_VtHi, g_VtHi);
    cudaGetSymbolAddress((void**)&p_Or, g_Or);
    cudaGetSymbolAddress((void**)&p_Oi, g_Oi);
    cudaGetSymbolAddress((void**)&p_y,  g_y);

    const int MF = BB * FF;      // 8196
    const int ML = BB * LL;      // 16384

    twiddle_init<<<9, 256>>>();
    ln_stats<<<BB * LL / 8, 256>>>(x);
    {
        dim3 g(EE / 32, LL / 32, BB), blk(32, 8);
        transpose_LE_to_EL_ln<<<g, blk>>>(x, gam, bet);
    }
    rfft_kernel<<<BB * EE, 256>>>();
    {
        GemmBatch gb;
        gb.g[0] = { p_xr, Wq_r, bq_r, p_Qhr, 1, 0.125f };
        gb.g[1] = { p_xi, Wq_i, bq_i, p_Qhi, 1, 0.125f };
        gb.g[2] = { p_xr, Wk_r, bk_r, p_Khr, 1, 1.0f };
        gb.g[3] = { p_xi, Wk_i, bk_i, p_Khi, 1, 1.0f };
        gb.g[4] = { p_xr, Wv_r, bv_r, p_VtHr, 2, 1.0f };
        gb.g[5] = { p_xi, Wv_i, bv_i, p_VtHi, 2, 1.0f };
        dim3 g((MF + 127) / 128, 8, 6);
        gemm_tc<<<g, 256>>>(gb, MF);
    }
    {
        dim3 g((FF + 127) / 128, BB * HH);
        attn_tc<<<g, 256, ATTN_SMEM>>>(p_Qhr, p_Qhi, p_Khr, p_Khi, p_Or, p_Oi);
    }
    irfft_kernel<<<BB * EE, 256>>>();
    {
        dim3 g(LL / 32, EE / 32, BB), blk(32, 8);
        transpose_EL_to_LE<<<g, blk>>>();
    }
    {
        GemmBatch gb;
        gb.g[0] = { p_y, Wo, nullptr, out, 0, 1.0f };
        gb.g[1] = gb.g[0]; gb.g[2] = gb.g[0]; gb.g[3] = gb.g[0];
        gb.g[4] = gb.g[0]; gb.g[5] = gb.g[0];
        dim3 g((ML + 127) / 128, 8, 1);
        gemm_tc<<<g, 256>>>(gb, ML);
    }
}

// round 17
// speedup vs baseline: 2.8433x; 1.0392x over previous
#include <cuda_runtime.h>
#include <cuda_fp16.h>
#include <math.h>
#include <stdint.h>
#include <string.h>

// ---------------- problem constants ----------------
#define BB 4
#define LL 4096
#define EE 512
#define FF 2049
#define FFP 2064           // padded F for transposed V
#define HH 8
#define DD 64
#define FFTM 2048

// ---------------- scratch (device globals; allocation-free) ----------------
__device__ float2 g_stats[BB * LL];            // (mean, rstd) per row
__device__ float g_xt[BB * EE * LL];
__device__ float g_xr[BB * FF * EE];
__device__ float g_xi[BB * FF * EE];
__device__ __half g_Qhr[BB * FF * EE];
__device__ __half g_Qhi[BB * FF * EE];
__device__ __half g_Khr[BB * FF * EE];
__device__ __half g_Khi[BB * FF * EE];
__device__ __half g_VtHr[BB * HH * DD * FFP];   // V transposed [bh][d][FFP]
__device__ __half g_VtHi[BB * HH * DD * FFP];
__device__ float g_Or[BB * FF * EE];
__device__ float g_Oi[BB * FF * EE];
__device__ float g_y [BB * LL * EE];
__device__ float2 g_twS[1536];                  // exp(-2*pi*i*j/2048), j<1536
__device__ float2 g_twP[FF];

// ---------------- helpers ----------------
__device__ __forceinline__ uint32_t h2u(__half2 h) {
    uint32_t u;
    memcpy(&u, &h, 4);
    return u;
}
__device__ __forceinline__ void mma16(float* c, const uint32_t* a, const uint32_t* b) {
    asm volatile(
        "mma.sync.aligned.m16n8k16.row.col.f32.f16.f16.f32 "
        "{%0,%1,%2,%3},{%4,%5,%6,%7},{%8,%9},{%0,%1,%2,%3};"
        : "+f"(c[0]), "+f"(c[1]), "+f"(c[2]), "+f"(c[3])
        : "r"(a[0]), "r"(a[1]), "r"(a[2]), "r"(a[3]),
          "r"(b[0]), "r"(b[1]));
}
__device__ __forceinline__ void ldsm4(uint32_t addr, uint32_t* r) {
    asm volatile("ldmatrix.sync.aligned.m8n8.x4.shared.b16 {%0,%1,%2,%3}, [%4];"
                 : "=r"(r[0]), "=r"(r[1]), "=r"(r[2]), "=r"(r[3]) : "r"(addr));
}
__device__ __forceinline__ uint32_t smem_u32(const void* p) {
    uint32_t a;
    asm("{ .reg .u64 t; cvta.to.shared.u64 t, %1; cvt.u32.u64 %0, t; }" : "=r"(a) : "l"(p));
    return a;
}
__device__ __forceinline__ void cpa16(uint32_t dst, const void* src, uint32_t bytes) {
    asm volatile("cp.async.cg.shared.global [%0], [%1], 16, %2;"
                 :: "r"(dst), "l"(src), "r"(bytes) : "memory");
}
#define CP_COMMIT()  asm volatile("cp.async.commit_group;" ::: "memory")
#define CP_WAITALL() asm volatile("cp.async.wait_all;" ::: "memory")
__device__ __forceinline__ float2 cmul(float2 a, float2 w) {
    return make_float2(a.x * w.x - a.y * w.y, a.x * w.y + a.y * w.x);
}

// ---------------- twiddle table init ----------------
__global__ void twiddle_init()
{
    int t = blockIdx.x * 256 + threadIdx.x;
    if (t < 1536) {
        float sn, cs; sincospif(-(float)t * (1.0f / 1024.0f), &sn, &cs);
        g_twS[t] = make_float2(cs, sn);
    }
    if (t < FF) {
        float sn, cs; sincospif(-(float)t * (1.0f / 2048.0f), &sn, &cs);
        g_twP[t] = make_float2(cs, sn);
    }
}

// ---------------- LayerNorm stats (warp per row) ----------------
__global__ void ln_stats(const float* __restrict__ x)
{
    int row = blockIdx.x * 8 + (threadIdx.x >> 5);
    int lane = threadIdx.x & 31;
    const float4* xr = (const float4*)(x + (size_t)row * EE);
    float s = 0.f, s2 = 0.f;
#pragma unroll
    for (int i = 0; i < 4; i++) {
        float4 v = xr[lane + i * 32];
        s  += v.x + v.y + v.z + v.w;
        s2 += v.x * v.x + v.y * v.y + v.z * v.z + v.w * v.w;
    }
#pragma unroll
    for (int off = 16; off; off >>= 1) {
        s  += __shfl_xor_sync(0xffffffffu, s,  off);
        s2 += __shfl_xor_sync(0xffffffffu, s2, off);
    }
    if (lane == 0) {
        float mean = s * (1.0f / EE);
        float var  = s2 * (1.0f / EE) - mean * mean;
        g_stats[row] = make_float2(mean, rsqrtf(var + 1e-5f));
    }
}

// ---------------- fused LN + transpose [B][L][E] -> [B][E][L] ----------------
__global__ void transpose_LE_to_EL_ln(const float* __restrict__ x,
                                      const float* __restrict__ gam,
                                      const float* __restrict__ bet)
{
    __shared__ float tile[32][33];
    int b  = blockIdx.z;
    int e0 = blockIdx.x * 32;
    int l0 = blockIdx.y * 32;
    const float* s = x + ((size_t)b * LL + l0) * EE + e0;
    float gv = gam[e0 + threadIdx.x];
    float bv = bet[e0 + threadIdx.x];
    for (int rr = threadIdx.y; rr < 32; rr += 8) {
        float2 st = g_stats[b * LL + l0 + rr];
        tile[rr][threadIdx.x] = (s[(size_t)rr * EE + threadIdx.x] - st.x) * st.y * gv + bv;
    }
    __syncthreads();
    float* d = g_xt + ((size_t)b * EE + e0) * LL + l0;
    for (int rr = threadIdx.y; rr < 32; rr += 8)
        d[(size_t)rr * LL + threadIdx.x] = tile[threadIdx.x][rr];
}

__global__ void transpose_EL_to_LE()
{
    __shared__ float tile[32][33];
    int b  = blockIdx.z;
    int l0 = blockIdx.x * 32;
    int e0 = blockIdx.y * 32;
    const float* s = g_xt + ((size_t)b * EE + e0) * LL + l0;
    for (int rr = threadIdx.y; rr < 32; rr += 8)
        tile[rr][threadIdx.x] = s[(size_t)rr * LL + threadIdx.x];
    __syncthreads();
    float* d = g_y + ((size_t)b * LL + l0) * EE + e0;
    for (int rr = threadIdx.y; rr < 32; rr += 8)
        d[(size_t)rr * EE + threadIdx.x] = tile[threadIdx.x][rr];
}

// ---------------- Stockham FFT radix-4 (complex 2048, 256 threads) ----------------
// sgn = +1 forward (tw = e^{-}), -1 inverse (tw = conj). 5 radix-4 stages + 1 radix-2.
__device__ __forceinline__ float2* fft2048_r4(float2* src, float2* dst,
                                              const float2* __restrict__ tw, int t, float sgn)
{
#pragma unroll 1
    for (int st = 0; st < 5; st++) {
        int sh = 2 * st;
        int s = 1 << sh;
#pragma unroll
        for (int i = 0; i < 2; i++) {
            int j = t + (i << 8);              // 0..511
            int p = j >> sh;
            int q = j & (s - 1);
            int base = q + (p << sh);
            float2 x0 = src[base];
            float2 x1 = src[base + 512];
            float2 x2 = src[base + 1024];
            float2 x3 = src[base + 1536];
            float2 t0 = make_float2(x0.x + x2.x, x0.y + x2.y);
            float2 t1 = make_float2(x0.x - x2.x, x0.y - x2.y);
            float2 t2 = make_float2(x1.x + x3.x, x1.y + x3.y);
            float2 t3 = make_float2(x1.x - x3.x, x1.y - x3.y);
            float2 m1 = make_float2(sgn * t3.y, -sgn * t3.x);   // -/+ i*t3
            int tb = p << sh;                    // p*s
            float2 w1 = tw[tb];
            float2 w2 = tw[2 * tb];
            float2 w3 = tw[3 * tb];
            int o = q + (p << (sh + 2));
            dst[o]          = make_float2(t0.x + t2.x, t0.y + t2.y);
            dst[o + s]      = cmul(make_float2(t1.x + m1.x, t1.y + m1.y), w1);
            dst[o + 2 * s]  = cmul(make_float2(t0.x - t2.x, t0.y - t2.y), w2);
            dst[o + 3 * s]  = cmul(make_float2(t1.x - m1.x, t1.y - m1.y), w3);
        }
        __syncthreads();
        float2* tmp = src; src = dst; dst = tmp;
    }
    // final radix-2 (s=1024, no twiddle)
#pragma unroll
    for (int i = 0; i < 4; i++) {
        int j = t + (i << 8);                   // 0..1023
        float2 u = src[j], v = src[j + 1024];
        dst[j]        = make_float2(u.x + v.x, u.y + v.y);
        dst[j + 1024] = make_float2(u.x - v.x, u.y - v.y);
    }
    __syncthreads();
    return dst;
}

__global__ void rfft_kernel()
{
    __shared__ float2 bufA[FFTM], bufB[FFTM];
    __shared__ float2 tw[1536];
    int t  = threadIdx.x;
    int be = blockIdx.x;
    int b  = be >> 9, e = be & 511;

    const float2* src = (const float2*)(g_xt + (size_t)be * LL);
#pragma unroll
    for (int i = 0; i < 8; i++) bufA[t + (i << 8)] = src[t + (i << 8)];
#pragma unroll
    for (int i = 0; i < 6; i++) tw[t + (i << 8)] = g_twS[t + (i << 8)];
    __syncthreads();
    float2* Z = fft2048_r4(bufA, bufB, tw, t, 1.0f);

    const float scale = 1.0f / 64.0f;
    for (int k = t; k <= FFTM; k += 256) {
        float2 zk = Z[k & (FFTM - 1)];
        float2 zm = Z[(FFTM - k) & (FFTM - 1)];
        float Er  = 0.5f * (zk.x + zm.x);
        float Eii = 0.5f * (zk.y - zm.y);
        float Or0 = 0.5f * (zk.x - zm.x);
        float Oi0 = 0.5f * (zk.y + zm.y);
        float2 w = g_twP[k];
        float ux = w.x * Or0 - w.y * Oi0;
        float uy = w.x * Oi0 + w.y * Or0;
        size_t g = ((size_t)b * FF + k) * EE + e;
        g_xr[g] = (Er  + uy) * scale;
        g_xi[g] = (Eii - ux) * scale;
    }
}

__global__ void irfft_kernel()
{
    __shared__ float2 bufA[FFTM], bufB[FFTM];
    __shared__ float2 tw[1536];
    int t  = threadIdx.x;
    int be = blockIdx.x;
    int b  = be >> 9, e = be & 511;

#pragma unroll
    for (int i = 0; i < 6; i++) {
        float2 w = g_twS[t + (i << 8)];
        tw[t + (i << 8)] = make_float2(w.x, -w.y);     // conj -> e^{+}
    }
    for (int k = t; k < FFTM; k += 256) {
        size_t gk = ((size_t)b * FF + k) * EE + e;
        size_t gm = ((size_t)b * FF + (FFTM - k)) * EE + e;
        float Xr_k = g_Or[gk];
        float Xi_k = (k == 0) ? 0.0f : g_Oi[gk];
        float Xr_m = g_Or[gm];
        float Xi_m = (k == 0) ? 0.0f : g_Oi[gm];
        float Er  = 0.5f * (Xr_k + Xr_m);
        float Ei  = 0.5f * (Xi_k - Xi_m);
        float Or0 = 0.5f * (Xr_k - Xr_m);
        float Oi0 = 0.5f * (Xi_k + Xi_m);
        float2 w = g_twP[k];
        float cs = w.x, sn = -w.y;
        float ux = cs * Or0 - sn * Oi0;
        float uy = cs * Oi0 + sn * Or0;
        bufA[k] = make_float2(Er - uy, Ei + ux);
    }
    __syncthreads();
    float2* w = fft2048_r4(bufA, bufB, tw, t, -1.0f);

    float2* out = (float2*)(g_xt + (size_t)be * LL);
    const float sc = 1.0f / 32.0f;
#pragma unroll
    for (int i = 0; i < 8; i++) {
        int n = t + (i << 8);
        float2 z = w[n];
        out[n] = make_float2(z.x * sc, z.y * sc);
    }
}

// ---------------- fp16 GEMM (ldmatrix + m16n8k16), batched; epilogue modes ----------------
struct GemmPtrs { const float *A, *W, *bias; void *C; int mode; float scale; };
struct GemmBatch { GemmPtrs g[6]; };

#define GLD 72
__global__ void __launch_bounds__(256) gemm_tc(GemmBatch batch, int M)
{
    __shared__ __half sA[128 * GLD];
    __shared__ __half sB[64 * GLD];
    GemmPtrs gp = batch.g[blockIdx.z];
    int m0 = blockIdx.x * 128, n0 = blockIdx.y * 64;
    int t = threadIdx.x, lane = t & 31, w = t >> 5;
    int g = lane >> 2, t4 = lane & 3;
    int wm = w >> 1, wn = w & 1;
    uint32_t sbA = smem_u32(sA), sbB = smem_u32(sB);

    int lrow = (lane & 7) + ((lane >> 3) & 1) * 8;
    int lcol = (lane >> 4) * 8;
    uint32_t lofs2 = (uint32_t)(lrow * GLD + lcol) * 2u;

    float acc[2][4][4] = {};

    for (int k0 = 0; k0 < 512; k0 += 64) {
#pragma unroll
        for (int i = 0; i < 8; i++) {
            int id = t + i * 256;
            int r = id >> 4, c4 = (id & 15) * 4;
            float4 v = make_float4(0.f, 0.f, 0.f, 0.f);
            if (m0 + r < M) v = *(const float4*)&gp.A[(size_t)(m0 + r) * 512 + k0 + c4];
            *(__half2*)(sA + r * GLD + c4)     = __floats2half2_rn(v.x, v.y);
            *(__half2*)(sA + r * GLD + c4 + 2) = __floats2half2_rn(v.z, v.w);
        }
#pragma unroll
        for (int i = 0; i < 4; i++) {
            int id = t + i * 256;
            int r = id >> 4, c4 = (id & 15) * 4;
            float4 v = *(const float4*)&gp.W[(size_t)(n0 + r) * 512 + k0 + c4];
            *(__half2*)(sB + r * GLD + c4)     = __floats2half2_rn(v.x, v.y);
            *(__half2*)(sB + r * GLD + c4 + 2) = __floats2half2_rn(v.z, v.w);
        }
        __syncthreads();
#pragma unroll
        for (int ks = 0; ks < 4; ks++) {
            uint32_t aF[2][4];
#pragma unroll
            for (int mt = 0; mt < 2; mt++)
                ldsm4(sbA + (uint32_t)((wm * 32 + mt * 16) * GLD + ks * 16) * 2u + lofs2, aF[mt]);
            uint32_t bF[2][4];
#pragma unroll
            for (int ntp = 0; ntp < 2; ntp++)
                ldsm4(sbB + (uint32_t)((wn * 32 + ntp * 16) * GLD + ks * 16) * 2u + lofs2, bF[ntp]);
#pragma unroll
            for (int mt = 0; mt < 2; mt++)
#pragma unroll
                for (int ntp = 0; ntp < 2; ntp++)
#pragma unroll
                    for (int sub = 0; sub < 2; sub++) {
                        uint32_t b2[2] = { bF[ntp][sub], bF[ntp][sub + 2] };
                        mma16(acc[mt][ntp * 2 + sub], aF[mt], b2);
                    }
        }
        __syncthreads();
    }
#pragma unroll
    for (int nt = 0; nt < 4; nt++) {
        int col = n0 + wn * 32 + nt * 8 + 2 * t4;
        float b0 = gp.bias ? gp.bias[col] : 0.f;
        float b1 = gp.bias ? gp.bias[col + 1] : 0.f;
#pragma unroll
        for (int mt = 0; mt < 2; mt++) {
#pragma unroll
            for (int half = 0; half < 2; half++) {
                int row = m0 + wm * 32 + mt * 16 + half * 8 + g;
                if (row >= M) continue;
                float v0 = acc[mt][nt][half * 2 + 0] + b0;
                float v1 = acc[mt][nt][half * 2 + 1] + b1;
                if (gp.mode == 0) {
                    *(float2*)((float*)gp.C + (size_t)row * 512 + col) = make_float2(v0, v1);
                } else if (gp.mode == 1) {
                    *(__half2*)((__half*)gp.C + (size_t)row * 512 + col) =
                        __floats2half2_rn(v0 * gp.scale, v1 * gp.scale);
                } else {
                    int bb = row / FF, f = row - bb * FF;
                    int hh = col >> 6, dd = col & 63;
                    __half* vh = (__half*)gp.C;
                    size_t gbase = ((size_t)((bb * 8 + hh) * 64 + dd)) * FFP + f;
                    vh[gbase]       = __float2half_rn(v0);
                    vh[gbase + FFP] = __float2half_rn(v1);
                }
            }
        }
    }
}

// ---------------- fp16 flash attention: 8x1 warp grid, register P ----------------
// smem: Qr 18432 | Qi 18432 | K0 18432 | K1 18432 | V 18432 = 92160 B
#define OQR 0
#define OQI 18432
#define OK0 36864
#define OK1 55296
#define OV  73728
#define ATTN_SMEM 92160
__global__ void __launch_bounds__(256) attn_tc(
    const __half* __restrict__ Qhr, const __half* __restrict__ Qhi,
    const __half* __restrict__ Khr, const __half* __restrict__ Khi,
    float* __restrict__ Outr, float* __restrict__ Outi)
{
    extern __shared__ char smc[];
    int bh = blockIdx.y;
    int b = bh >> 3, h = bh & 7;
    int q0 = blockIdx.x * 128;
    int t = threadIdx.x, lane = t & 31, w = t >> 5;
    int g = lane >> 2, tg = lane & 3;
    const size_t baseF = (size_t)b * FF * EE + h * DD;
    const size_t baseH = (size_t)(b * FF) * 512 + h * 64;

    uint32_t sb = smem_u32(smc);
    uint32_t aK[2] = { sb + OK0, sb + OK1 };
    uint32_t aV = sb + OV;

    int lrow = (lane & 7) + ((lane >> 3) & 1) * 8;
    int lcol = (lane >> 4) * 8;
    uint32_t lofs2 = (uint32_t)(lrow * 72 + lcol) * 2u;

    auto issueK = [&](int kt, int p) {
#pragma unroll
        for (int j = 0; j < 4; j++) {
            int idx = t + j * 256;
            int comp = idx >> 9;
            int rem = idx & 511;
            int f = rem >> 3, c = rem & 7;
            int gf = kt * 64 + f;
            const __half* srcb = comp ? Khi : Khr;
            const __half* src = srcb;
            uint32_t bytes = 0;
            if (gf < FF) { src = srcb + baseH + (size_t)gf * 512 + c * 8; bytes = 16; }
            cpa16(aK[p] + (uint32_t)(comp * 4608 + f * 72 + c * 8) * 2u, src, bytes);
        }
    };
    auto issueV = [&](int f0) {
#pragma unroll
        for (int j = 0; j < 4; j++) {
            int idx = t + j * 256;
            int comp = idx >> 9;
            int rem = idx & 511;
            int d = rem >> 3, c = rem & 7;
            int fb = f0 + c * 8;
            const __half* srcb = comp ? g_VtHi : g_VtHr;
            const __half* src = srcb;
            uint32_t bytes = 0;
            if (fb < FF) {
                src = srcb + (size_t)(bh * 64 + d) * FFP + fb;
                bytes = (fb + 8 <= FF) ? 16u : (uint32_t)(FF - fb) * 2u;
            }
            cpa16(aV + (uint32_t)(comp * 4608 + d * 72 + c * 8) * 2u, src, bytes);
        }
    };

    issueK(0, 0);
    CP_COMMIT();

    __half* sQr = (__half*)smc;
    __half* sQi = (__half*)(smc + OQI);
    for (int idx = t; idx < 4096; idx += 256) {
        int q = idx >> 5, c = idx & 31;
        int gq = q0 + q;
        __half2 vr = __floats2half2_rn(0.f, 0.f), vi = vr;
        if (gq < FF) {
            vr = *(const __half2*)(Qhr + baseH + (size_t)gq * 512 + 2 * c);
            vi = *(const __half2*)(Qhi + baseH + (size_t)gq * 512 + 2 * c);
        }
        *(__half2*)(sQr + q * 72 + 2 * c) = vr;
        *(__half2*)(sQi + q * 72 + 2 * c) = vi;
    }
    CP_WAITALL();

    float accR[8][4] = {}, accI[8][4] = {};
    float m_run[2] = { -1e30f, -1e30f };
    float l_run[2] = { 0.f, 0.f };

    for (int it = 0; it < 33; it++) {
        int p = it & 1;
        int f0 = it * 64;
        __syncthreads();
        if (it < 32) issueK(it + 1, p ^ 1);
        issueV(f0);
        CP_COMMIT();

        // ---- S = Qr Kr^T + Qi Ki^T  (warp rows w*16, all 64 cols) ----
        float sacc[8][4] = {};
#pragma unroll
        for (int ks = 0; ks < 4; ks++) {
            uint32_t aR[4], aI[4];
            uint32_t rofsA = (uint32_t)((w * 16) * 72 + ks * 16) * 2u + lofs2;
            ldsm4(sb + OQR + rofsA, aR);
            ldsm4(sb + OQI + rofsA, aI);
#pragma unroll
            for (int ntp = 0; ntp < 4; ntp++) {
                uint32_t bR[4], bI[4];
                uint32_t rofsB = (uint32_t)((ntp * 16) * 72 + ks * 16) * 2u + lofs2;
                ldsm4(aK[p] + rofsB, bR);
                ldsm4(aK[p] + 9216u + rofsB, bI);
#pragma unroll
                for (int sub = 0; sub < 2; sub++) {
                    int nt = ntp * 2 + sub;
                    uint32_t b2r[2] = { bR[sub], bR[sub + 2] };
                    uint32_t b2i[2] = { bI[sub], bI[sub + 2] };
                    mma16(sacc[nt], aR, b2r);
                    mma16(sacc[nt], aI, b2i);
                }
            }
        }

        // ---- mask tail cols ----
        if (f0 + 64 > FF) {
#pragma unroll
            for (int nt = 0; nt < 8; nt++) {
                int cb = f0 + nt * 8 + 2 * tg;
                if (cb >= FF)     { sacc[nt][0] = -1e30f; sacc[nt][2] = -1e30f; }
                if (cb + 1 >= FF) { sacc[nt][1] = -1e30f; sacc[nt][3] = -1e30f; }
            }
        }

        // ---- warp-local softmax ----
        float rmax[2] = { -1e30f, -1e30f };
#pragma unroll
        for (int nt = 0; nt < 8; nt++) {
            rmax[0] = fmaxf(rmax[0], fmaxf(sacc[nt][0], sacc[nt][1]));
            rmax[1] = fmaxf(rmax[1], fmaxf(sacc[nt][2], sacc[nt][3]));
        }
#pragma unroll
        for (int off = 1; off < 4; off <<= 1) {
            rmax[0] = fmaxf(rmax[0], __shfl_xor_sync(0xffffffffu, rmax[0], off));
            rmax[1] = fmaxf(rmax[1], __shfl_xor_sync(0xffffffffu, rmax[1], off));
        }
        float alpha[2];
#pragma unroll
        for (int hh = 0; hh < 2; hh++) {
            float mnew = fmaxf(m_run[hh], rmax[hh]);
            alpha[hh] = __expf(m_run[hh] - mnew);
            m_run[hh] = mnew;
        }
        float rsum[2] = { 0.f, 0.f };
        uint32_t aP[4][4];
#pragma unroll
        for (int nt = 0; nt < 8; nt++) {
            float p0 = __expf(sacc[nt][0] - m_run[0]);
            float p1 = __expf(sacc[nt][1] - m_run[0]);
            float p2 = __expf(sacc[nt][2] - m_run[1]);
            float p3 = __expf(sacc[nt][3] - m_run[1]);
            rsum[0] += p0 + p1;
            rsum[1] += p2 + p3;
            int kc = nt >> 1, hi = (nt & 1) * 2;
            aP[kc][hi + 0] = h2u(__floats2half2_rn(p0, p1));
            aP[kc][hi + 1] = h2u(__floats2half2_rn(p2, p3));
        }
#pragma unroll
        for (int off = 1; off < 4; off <<= 1) {
            rsum[0] += __shfl_xor_sync(0xffffffffu, rsum[0], off);
            rsum[1] += __shfl_xor_sync(0xffffffffu, rsum[1], off);
        }
        l_run[0] = l_run[0] * alpha[0] + rsum[0];
        l_run[1] = l_run[1] * alpha[1] + rsum[1];
        // rescale accumulators
#pragma unroll
        for (int nt = 0; nt < 8; nt++) {
            accR[nt][0] *= alpha[0]; accR[nt][1] *= alpha[0];
            accR[nt][2] *= alpha[1]; accR[nt][3] *= alpha[1];
            accI[nt][0] *= alpha[0]; accI[nt][1] *= alpha[0];
            accI[nt][2] *= alpha[1]; accI[nt][3] *= alpha[1];
        }
        CP_WAITALL();
        __syncthreads();

        // ---- O += P @ V  (P in registers) ----
#pragma unroll
        for (int kc = 0; kc < 4; kc++) {
#pragma unroll
            for (int ntp = 0; ntp < 4; ntp++) {
                uint32_t bVr[4], bVi[4];
                uint32_t rofs = (uint32_t)((ntp * 16) * 72 + kc * 16) * 2u + lofs2;
                ldsm4(aV + rofs, bVr);
                ldsm4(aV + 9216u + rofs, bVi);
#pragma unroll
                for (int sub = 0; sub < 2; sub++) {
                    int nt = ntp * 2 + sub;
                    uint32_t b2r[2] = { bVr[sub], bVr[sub + 2] };
                    uint32_t b2i[2] = { bVi[sub], bVi[sub + 2] };
                    mma16(accR[nt], aP[kc], b2r);
                    mma16(accI[nt], aP[kc], b2i);
                }
            }
        }
    }

    // ---- epilogue ----
    float li0 = 1.0f / l_run[0];
    float li1 = 1.0f / l_run[1];
    int qrow = q0 + w * 16 + g;
#pragma unroll
    for (int nt = 0; nt < 8; nt++) {
        int col = nt * 8 + 2 * tg;
        if (qrow < FF) {
            size_t gg = baseF + (size_t)qrow * EE + col;
            *(float2*)&Outr[gg] = make_float2(accR[nt][0] * li0, accR[nt][1] * li0);
            *(float2*)&Outi[gg] = make_float2(accI[nt][0] * li0, accI[nt][1] * li0);
        }
        if (qrow + 8 < FF) {
            size_t gg = baseF + (size_t)(qrow + 8) * EE + col;
            *(float2*)&Outr[gg] = make_float2(accR[nt][2] * li1, accR[nt][3] * li1);
            *(float2*)&Outi[gg] = make_float2(accI[nt][2] * li1, accI[nt][3] * li1);
        }
    }
}

// ---------------- host launcher ----------------
extern "C" void kernel_launch(void* const* d_in, const int* in_sizes, int n_in,
                              void* d_out, int out_size)
{
    const float* x    = (const float*)d_in[0];
    const float* gam  = (const float*)d_in[1];
    const float* bet  = (const float*)d_in[2];
    const float* Wq_r = (const float*)d_in[3];
    const float* bq_r = (const float*)d_in[4];
    const float* Wq_i = (const float*)d_in[5];
    const float* bq_i = (const float*)d_in[6];
    const float* Wk_r = (const float*)d_in[7];
    const float* bk_r = (const float*)d_in[8];
    const float* Wk_i = (const float*)d_in[9];
    const float* bk_i = (const float*)d_in[10];
    const float* Wv_r = (const float*)d_in[11];
    const float* bv_r = (const float*)d_in[12];
    const float* Wv_i = (const float*)d_in[13];
    const float* bv_i = (const float*)d_in[14];
    const float* Wo   = (const float*)d_in[15];
    float* out = (float*)d_out;

    static int attr_set = 0;
    if (!attr_set) {
        cudaFuncSetAttribute(attn_tc, cudaFuncAttributeMaxDynamicSharedMemorySize, ATTN_SMEM);
        attr_set = 1;
    }

    float *p_xr, *p_xi, *p_Or, *p_Oi, *p_y;
    __half *p_Qhr, *p_Qhi, *p_Khr, *p_Khi, *p_VtHr, *p_VtHi;
    cudaGetSymbolAddress((void**)&p_xr, g_xr);
    cudaGetSymbolAddress((void**)&p_xi, g_xi);
    cudaGetSymbolAddress((void**)&p_Qhr, g_Qhr);
    cudaGetSymbolAddress((void**)&p_Qhi, g_Qhi);
    cudaGetSymbolAddress((void**)&p_Khr, g_Khr);
    cudaGetSymbolAddress((void**)&p_Khi, g_Khi);
    cudaGetSymbolAddress((void**)&p_VtHr, g_VtHr);
    cudaGetSymbolAddress((void**)&p_VtHi, g_VtHi);
    cudaGetSymbolAddress((void**)&p_Or, g_Or);
    cudaGetSymbolAddress((void**)&p_Oi, g_Oi);
    cudaGetSymbolAddress((void**)&p_y,  g_y);

    const int MF = BB * FF;      // 8196
    const int ML = BB * LL;      // 16384

    twiddle_init<<<9, 256>>>();
    ln_stats<<<BB * LL / 8, 256>>>(x);
    {
        dim3 g(EE / 32, LL / 32, BB), blk(32, 8);
        transpose_LE_to_EL_ln<<<g, blk>>>(x, gam, bet);
    }
    rfft_kernel<<<BB * EE, 256>>>();
    {
        GemmBatch gb;
        gb.g[0] = { p_xr, Wq_r, bq_r, p_Qhr, 1, 0.125f };
        gb.g[1] = { p_xi, Wq_i, bq_i, p_Qhi, 1, 0.125f };
        gb.g[2] = { p_xr, Wk_r, bk_r, p_Khr, 1, 1.0f };
        gb.g[3] = { p_xi, Wk_i, bk_i, p_Khi, 1, 1.0f };
        gb.g[4] = { p_xr, Wv_r, bv_r, p_VtHr, 2, 1.0f };
        gb.g[5] = { p_xi, Wv_i, bv_i, p_VtHi, 2, 1.0f };
        dim3 g((MF + 127) / 128, 8, 6);
        gemm_tc<<<g, 256>>>(gb, MF);
    }
    {
        dim3 g((FF + 127) / 128, BB * HH);
        attn_tc<<<g, 256, ATTN_SMEM>>>(p_Qhr, p_Qhi, p_Khr, p_Khi, p_Or, p_Oi);
    }
    irfft_kernel<<<BB * EE, 256>>>();
    {
        dim3 g(LL / 32, EE / 32, BB), blk(32, 8);
        transpose_EL_to_LE<<<g, blk>>>();
    }
    {
        GemmBatch gb;
        gb.g[0] = { p_y, Wo, nullptr, out, 0, 1.0f };
        gb.g[1] = gb.g[0]; gb.g[2] = gb.g[0]; gb.g[3] = gb.g[0];
        gb.g[4] = gb.g[0]; gb.g[5] = gb.g[0];
        dim3 g((ML + 127) / 128, 8, 1);
        gemm_tc<<<g, 256>>>(gb, ML);
    }
}